// round 11
// baseline (speedup 1.0000x reference)
#include <cuda_runtime.h>
#include <cuda_bf16.h>
#include <cstdint>
#include <math.h>

__device__ __forceinline__ uint32_t smem_to_u32(const void* p) {
    uint32_t a;
    asm("{ .reg .u64 t; cvta.to.shared.u64 t, %1; cvt.u32.u64 %0, t; }" : "=r"(a) : "l"(p));
    return a;
}
#define CP_ASYNC16(d, s) asm volatile("cp.async.cg.shared.global [%0], [%1], 16;" :: "r"(d), "l"(s))
#define CP_COMMIT() asm volatile("cp.async.commit_group;")
#define CP_WAIT(N)  asm volatile("cp.async.wait_group %0;" :: "n"(N))
#define LDSM4(R0,R1,R2,R3,A) \
    asm volatile("ldmatrix.sync.aligned.m8n8.x4.shared.b16 {%0,%1,%2,%3}, [%4];" \
        : "=r"(R0),"=r"(R1),"=r"(R2),"=r"(R3) : "r"(A))
#define LDSM4T(R0,R1,R2,R3,A) \
    asm volatile("ldmatrix.sync.aligned.m8n8.x4.trans.shared.b16 {%0,%1,%2,%3}, [%4];" \
        : "=r"(R0),"=r"(R1),"=r"(R2),"=r"(R3) : "r"(A))
#define MMA16816(D,A0,A1,A2,A3,B0,B1) \
    asm volatile("mma.sync.aligned.m16n8k16.row.col.f32.bf16.bf16.f32 " \
        "{%0,%1,%2,%3}, {%4,%5,%6,%7}, {%8,%9}, {%0,%1,%2,%3};" \
        : "+f"((D)[0]),"+f"((D)[1]),"+f"((D)[2]),"+f"((D)[3]) \
        : "r"(A0),"r"(A1),"r"(A2),"r"(A3),"r"(B0),"r"(B1))

__device__ __forceinline__ void pack_hilo(float v0, float v1, uint32_t& hi, uint32_t& lo) {
    uint32_t h;
    asm("cvt.rn.bf16x2.f32 %0, %1, %2;" : "=r"(h) : "f"(v1), "f"(v0));
    float l0 = v0 - __uint_as_float(h << 16);
    float l1 = v1 - __uint_as_float(h & 0xffff0000u);
    asm("cvt.rn.bf16x2.f32 %0, %1, %2;" : "=r"(lo) : "f"(l1), "f"(l0));
    hi = h;
}

// ---------------- scratch ----------------
#define QKV_ELEMS (8u * 1024u * 1024u)
#define UW_ELEMS  (108ull * 1024u * 1024u)
#define VW_ELEMS  (108ull * 512u * 1024u)
__device__ __align__(128) __nv_bfloat16 g_uwh[UW_ELEMS], g_uwl[UW_ELEMS];
__device__ __align__(128) __nv_bfloat16 g_vwh[VW_ELEMS], g_vwl[VW_ELEMS];
__device__ __align__(128) float g_mw[108ull * 1024u * 512u];
__device__ __align__(128) __nv_bfloat16 g_qh[QKV_ELEMS], g_ql[QKV_ELEMS];
__device__ __align__(128) __nv_bfloat16 g_kh[QKV_ELEMS], g_kl[QKV_ELEMS];
__device__ __align__(128) __nv_bfloat16 g_vh[QKV_ELEMS], g_vl[QKV_ELEMS];
__device__ __align__(128) __nv_bfloat16 g_aoh[QKV_ELEMS], g_aol[QKV_ELEMS];
__device__ __align__(128) __nv_bfloat16 g_woh[1024u*1024u], g_wol[1024u*1024u];
__device__ __align__(128) uint32_t g_mb[8u * 1024u * 32u];

// ---------------- Winograd transform helpers ----------------
__device__ __forceinline__ void gtrans(float a, float b, float d, float* y) {
    const float s6 = 1.f / 6.f, s12 = 1.f / 12.f, s24 = 1.f / 24.f;
    y[0] = 0.25f * a;
    y[1] = -(a + b + d) * s6;
    y[2] = (-a + b - d) * s6;
    y[3] = a * s24 + b * s12 + d * s6;
    y[4] = a * s24 - b * s12 + d * s6;
    y[5] = d;
}
__device__ __forceinline__ void btrans(const float* x, float* y) {
    y[0] = 4.f * x[0] - 5.f * x[2] + x[4];
    y[1] = -4.f * x[1] - 4.f * x[2] + x[3] + x[4];
    y[2] = 4.f * x[1] - 4.f * x[2] - x[3] + x[4];
    y[3] = -2.f * x[1] - x[2] + 2.f * x[3] + x[4];
    y[4] = 2.f * x[1] - x[2] - 2.f * x[3] + x[4];
    y[5] = 4.f * x[1] - 5.f * x[3] + x[5];
}
__device__ __forceinline__ void atrans(const float* x, float* y) {
    y[0] = x[0] + x[1] + x[2] + x[3] + x[4];
    y[1] = x[1] - x[2] + 2.f * x[3] - 2.f * x[4];
    y[2] = x[1] + x[2] + 4.f * x[3] + 4.f * x[4];
    y[3] = x[1] - x[2] + 8.f * x[3] - 8.f * x[4] + x[5];
}

// ====================================================================
// Merged prep kernel: [0,6144) wino_x, [6144,18432) wino_w,
// [18432,22528) pack_wo, [22528,55296) pack_mask. All independent.
// ====================================================================
__global__ __launch_bounds__(256)
void prep_kernel(const float* __restrict__ q, const float* __restrict__ k,
                 const float* __restrict__ v,
                 const float* __restrict__ Wq, const float* __restrict__ Wk,
                 const float* __restrict__ Wv, const float* __restrict__ Wo,
                 const int* __restrict__ mask,
                 __nv_bfloat16* __restrict__ vwh, __nv_bfloat16* __restrict__ vwl,
                 __nv_bfloat16* __restrict__ uh,  __nv_bfloat16* __restrict__ ul,
                 __nv_bfloat16* __restrict__ woh, __nv_bfloat16* __restrict__ wol,
                 uint32_t* __restrict__ mb) {
    __shared__ float xs[6][32][34];
    const int bx = blockIdx.x, tid = threadIdx.x;

    if (bx < 6144) {
        // ---- wino_x: V = B^T d B ----
        const int ty = bx & 7, ci0 = ((bx >> 3) & 31) * 32;
        const int zz = bx >> 8;
        const int conv = zz >> 3, b = zz & 7;
        const float* x = conv == 0 ? q : (conv == 1 ? k : v);
        for (int l = tid; l < 6 * 32 * 34; l += 256) {
            int u = l / 1088;
            int rem = l - u * 1088;
            int ci = rem / 34, cc = rem - ci * 34;
            int gr = 4 * ty - 1 + u, gc = cc - 1;
            float val = 0.f;
            if ((unsigned)gr < 32u && (unsigned)gc < 32u)
                val = x[((size_t)(b * 1024 + ci0 + ci)) * 1024 + gr * 32 + gc];
            xs[u][ci][cc] = val;
        }
        __syncthreads();
        const int tx = tid >> 5, ci = tid & 31;
        float d[6][6];
        #pragma unroll
        for (int u = 0; u < 6; u++)
            #pragma unroll
            for (int vv = 0; vv < 6; vv++) d[u][vv] = xs[u][ci][4 * tx + vv];
        float t1[6][6];
        #pragma unroll
        for (int vv = 0; vv < 6; vv++) {
            float col[6] = {d[0][vv], d[1][vv], d[2][vv], d[3][vv], d[4][vv], d[5][vv]};
            float y[6];
            btrans(col, y);
            #pragma unroll
            for (int u = 0; u < 6; u++) t1[u][vv] = y[u];
        }
        const size_t tile = (size_t)b * 64 + ty * 8 + tx;
        #pragma unroll
        for (int u = 0; u < 6; u++) {
            float y[6];
            btrans(t1[u], y);
            #pragma unroll
            for (int vv = 0; vv < 6; vv++) {
                int kk = u * 6 + vv;
                size_t o = ((size_t)(conv * 36 + kk) * 512 + tile) * 1024 + ci0 + ci;
                __nv_bfloat16 h = __float2bfloat16(y[vv]);
                vwh[o] = h;
                vwl[o] = __float2bfloat16(y[vv] - __bfloat162float(h));
            }
        }
    } else if (bx < 18432) {
        // ---- wino_w: U = G g G^T ----
        int i = (bx - 6144) * 256 + tid;
        int conv = i >> 20;
        int co = (i >> 10) & 1023, ci = i & 1023;
        const float* W = conv == 0 ? Wq : (conv == 1 ? Wk : Wv);
        const float* g = W + ((size_t)co * 1024 + ci) * 9;
        float t[6][3];
        #pragma unroll
        for (int c = 0; c < 3; c++) {
            float col[6];
            gtrans(g[c], g[3 + c], g[6 + c], col);
            #pragma unroll
            for (int u = 0; u < 6; u++) t[u][c] = col[u];
        }
        #pragma unroll
        for (int u = 0; u < 6; u++) {
            float U[6];
            gtrans(t[u][0], t[u][1], t[u][2], U);
            #pragma unroll
            for (int vv = 0; vv < 6; vv++) {
                int kk = u * 6 + vv;
                size_t o = (((size_t)(conv * 36 + kk)) << 20) + ((size_t)co << 10) + ci;
                __nv_bfloat16 h = __float2bfloat16(U[vv]);
                uh[o] = h;
                ul[o] = __float2bfloat16(U[vv] - __bfloat162float(h));
            }
        }
    } else if (bx < 22528) {
        // ---- pack_wo ----
        int i = (bx - 18432) * 256 + tid;
        float w = Wo[i];
        __nv_bfloat16 h = __float2bfloat16(w);
        woh[i] = h;
        wol[i] = __float2bfloat16(w - __bfloat162float(h));
    } else {
        // ---- pack_mask ----
        int idx = (bx - 22528) * 256 + tid;
        uint32_t word = __ballot_sync(0xffffffffu, mask[idx] != 0);
        if ((tid & 31) == 0) mb[idx >> 5] = word;
    }
}

// ====================================================================
// Winograd batched GEMM: M[g] = U[g] * V[g]^T. 3-stage pipeline.
// ====================================================================
#define GEMM_SMEM_BYTES (3 * 4 * 16384)

__global__ __launch_bounds__(256, 1)
void wino_gemm_kernel(const __nv_bfloat16* __restrict__ uh, const __nv_bfloat16* __restrict__ ul,
                      const __nv_bfloat16* __restrict__ vwh, const __nv_bfloat16* __restrict__ vwl,
                      float* __restrict__ mw) {
    extern __shared__ char dsm[];
    const int tid = threadIdx.x, wid = tid >> 5, lane = tid & 31;
    const int m0 = blockIdx.x * 128, n0 = blockIdx.y * 128, gidx = blockIdx.z;
    const __nv_bfloat16* ah_g = uh  + ((size_t)gidx << 20);
    const __nv_bfloat16* al_g = ul  + ((size_t)gidx << 20);
    const __nv_bfloat16* bh_g = vwh + ((size_t)gidx << 19);
    const __nv_bfloat16* bl_g = vwl + ((size_t)gidx << 19);
    const uint32_t sbase = smem_to_u32(dsm);
    const int rowb = tid >> 3, seg = tid & 7;

    auto load_chunk = [&](int c, int buf) {
        const int ci0 = c << 6;
        const uint32_t sb = sbase + buf * 65536;
        #pragma unroll
        for (int i = 0; i < 4; i++) {
            int row = rowb + 32 * i;
            uint32_t sw = (uint32_t)(row * 128) + (uint32_t)(((seg ^ (row & 7)) << 4));
            size_t ao = (size_t)(m0 + row) * 1024 + ci0 + seg * 8;
            size_t bo = (size_t)(n0 + row) * 1024 + ci0 + seg * 8;
            CP_ASYNC16(sb + sw,         ah_g + ao);
            CP_ASYNC16(sb + 16384 + sw, al_g + ao);
            CP_ASYNC16(sb + 32768 + sw, bh_g + bo);
            CP_ASYNC16(sb + 49152 + sw, bl_g + bo);
        }
    };

    const int wm = (wid & 1) * 64, wn = (wid >> 1) * 32;
    int rowA[4], xorA[4];
    #pragma unroll
    for (int mt = 0; mt < 4; mt++) { rowA[mt] = wm + mt * 16 + (lane & 15); xorA[mt] = rowA[mt] & 7; }
    const int cgA = lane >> 4;
    int rowB[2], xorB[2];
    #pragma unroll
    for (int np = 0; np < 2; np++) {
        rowB[np] = wn + np * 16 + (lane & 7) + ((lane >> 4) & 1) * 8;
        xorB[np] = rowB[np] & 7;
    }
    const int cgB = (lane >> 3) & 1;

    float acc[4][4][4];
    #pragma unroll
    for (int mt = 0; mt < 4; mt++)
        #pragma unroll
        for (int nt = 0; nt < 4; nt++)
            #pragma unroll
            for (int e = 0; e < 4; e++) acc[mt][nt][e] = 0.f;

    load_chunk(0, 0); CP_COMMIT();
    load_chunk(1, 1); CP_COMMIT();
    for (int c = 0; c < 16; ++c) {
        if (c == 15) { CP_WAIT(0); } else { CP_WAIT(1); }
        __syncthreads();
        if (c + 2 < 16) { load_chunk(c + 2, (c + 2) % 3); CP_COMMIT(); }
        const uint32_t sb = sbase + (c % 3) * 65536;
        const uint32_t aHi = sb, aLo = sb + 16384, bHi = sb + 32768, bLo = sb + 49152;
        #pragma unroll
        for (int ks = 0; ks < 4; ks++) {
            uint32_t ah[4][4], al[4][4], bh2[2][4], bl2[2][4];
            #pragma unroll
            for (int mt = 0; mt < 4; mt++) {
                uint32_t off = (uint32_t)(rowA[mt] * 128) + (uint32_t)(((ks*2+cgA) ^ xorA[mt]) << 4);
                LDSM4(ah[mt][0], ah[mt][1], ah[mt][2], ah[mt][3], aHi + off);
                LDSM4(al[mt][0], al[mt][1], al[mt][2], al[mt][3], aLo + off);
            }
            #pragma unroll
            for (int np = 0; np < 2; np++) {
                uint32_t off = (uint32_t)(rowB[np] * 128) + (uint32_t)(((ks*2+cgB) ^ xorB[np]) << 4);
                LDSM4(bh2[np][0], bh2[np][1], bh2[np][2], bh2[np][3], bHi + off);
                LDSM4(bl2[np][0], bl2[np][1], bl2[np][2], bl2[np][3], bLo + off);
            }
            #pragma unroll
            for (int mt = 0; mt < 4; mt++)
                #pragma unroll
                for (int nt = 0; nt < 4; nt++) {
                    const int np = nt >> 1, h = (nt & 1) * 2;
                    MMA16816(acc[mt][nt], ah[mt][0],ah[mt][1],ah[mt][2],ah[mt][3], bh2[np][h], bh2[np][h+1]);
                    MMA16816(acc[mt][nt], ah[mt][0],ah[mt][1],ah[mt][2],ah[mt][3], bl2[np][h], bl2[np][h+1]);
                    MMA16816(acc[mt][nt], al[mt][0],al[mt][1],al[mt][2],al[mt][3], bh2[np][h], bh2[np][h+1]);
                }
        }
    }

    float* outp = mw + (size_t)gidx * 1024 * 512;
    #pragma unroll
    for (int mt = 0; mt < 4; mt++) {
        const int ma = m0 + wm + mt * 16 + (lane >> 2);
        const int mb2 = ma + 8;
        #pragma unroll
        for (int nt = 0; nt < 4; nt++) {
            const int n = n0 + wn + nt * 8 + 2 * (lane & 3);
            *(float2*)(outp + (size_t)ma  * 512 + n) = make_float2(acc[mt][nt][0], acc[mt][nt][1]);
            *(float2*)(outp + (size_t)mb2 * 512 + n) = make_float2(acc[mt][nt][2], acc[mt][nt][3]);
        }
    }
}

// ---------------- Winograd output transform: Y = A^T M A ----------------
__global__ __launch_bounds__(256)
void wino_out_kernel(const float* __restrict__ mw,
                     const float* __restrict__ bq, const float* __restrict__ bk,
                     const float* __restrict__ bv,
                     __nv_bfloat16* __restrict__ qh, __nv_bfloat16* __restrict__ ql,
                     __nv_bfloat16* __restrict__ kh, __nv_bfloat16* __restrict__ kl,
                     __nv_bfloat16* __restrict__ vh, __nv_bfloat16* __restrict__ vl) {
    const int idx = blockIdx.x * 256 + threadIdx.x;
    const int conv = idx >> 19;
    const int rem = idx & 0x7FFFF;
    const int co = rem >> 9;
    const int tile = rem & 511;

    float M[36];
    #pragma unroll
    for (int kk = 0; kk < 36; kk++)
        M[kk] = mw[(size_t)(conv * 36 + kk) * 524288 + (size_t)co * 512 + tile];

    float t[4][6];
    #pragma unroll
    for (int vv = 0; vv < 6; vv++) {
        float col[6] = {M[vv], M[6 + vv], M[12 + vv], M[18 + vv], M[24 + vv], M[30 + vv]};
        float y[4];
        atrans(col, y);
        #pragma unroll
        for (int r = 0; r < 4; r++) t[r][vv] = y[r];
    }

    __nv_bfloat16 *oh, *ol;
    const float* bias;
    if (conv == 0)      { oh = qh; ol = ql; bias = bq; }
    else if (conv == 1) { oh = kh; ol = kl; bias = bk; }
    else                { oh = vh; ol = vl; bias = bv; }
    const float scale = (conv == 0) ? 0.125f : 1.0f;
    const float bi = bias[co];

    const int b = tile >> 6, tt = tile & 63;
    const int tyy = tt >> 3, txx = tt & 7;
    size_t base = ((size_t)(b * 1024 + co)) * 1024 + (4 * tyy) * 32 + 4 * txx;
    #pragma unroll
    for (int r = 0; r < 4; r++) {
        float y[4];
        atrans(t[r], y);
        uint32_t h0, l0, h1, l1;
        pack_hilo((y[0] + bi) * scale, (y[1] + bi) * scale, h0, l0);
        pack_hilo((y[2] + bi) * scale, (y[3] + bi) * scale, h1, l1);
        size_t o = base + (size_t)r * 32;
        *(uint32_t*)(oh + o)     = h0;
        *(uint32_t*)(oh + o + 2) = h1;
        *(uint32_t*)(ol + o)     = l0;
        *(uint32_t*)(ol + o + 2) = l1;
    }
}

// ====================================================================
// Fused flash attention. KV chunk = 64 rows, 16 chunks, 2 CTAs/SM.
// smem: 2 x 32KB KV bufs + 32KB Q + 16.5KB mask = 112.5KB
// ====================================================================
#define FA_KVBUF 32768
#define FA_QOFF  (2 * FA_KVBUF)
#define FA_MOFF  (FA_QOFF + 32768)
#define FA_SMEM_BYTES (FA_MOFF + 128 * 33 * 4)

__global__ __launch_bounds__(256, 2)
void flash_kernel(const __nv_bfloat16* __restrict__ qh_g, const __nv_bfloat16* __restrict__ ql_g,
                  const __nv_bfloat16* __restrict__ kh_g, const __nv_bfloat16* __restrict__ kl_g,
                  const __nv_bfloat16* __restrict__ vh_g, const __nv_bfloat16* __restrict__ vl_g,
                  const uint32_t* __restrict__ mbits,
                  __nv_bfloat16* __restrict__ aoh_g, __nv_bfloat16* __restrict__ aol_g) {
    extern __shared__ char dsm[];
    const int tid = threadIdx.x, wid = tid >> 5, lane = tid & 31;
    const int t0 = blockIdx.x * 128, bh = blockIdx.y, b = bh >> 4, h = bh & 15;
    const uint32_t sb = smem_to_u32(dsm);
    uint32_t* msk = (uint32_t*)(dsm + FA_MOFF);
    const int rowb = tid >> 3, seg = tid & 7;
    const size_t rbase = (size_t)b * 1024;
    const int fcol = h * 64, wt0 = wid * 16;

    auto load_kv = [&](int c, int buf) {
        const uint32_t p = sb + buf * FA_KVBUF;
        const int s0 = c * 64;
        #pragma unroll
        for (int i = 0; i < 2; i++) {
            int row = rowb + 32 * i;
            uint32_t sw = (uint32_t)(row * 128) + (uint32_t)(((seg ^ (row & 7)) << 4));
            size_t go = (rbase + s0 + row) * 1024 + fcol + seg * 8;
            CP_ASYNC16(p + sw,         kh_g + go);
            CP_ASYNC16(p + 8192 + sw,  kl_g + go);
            CP_ASYNC16(p + 16384 + sw, vh_g + go);
            CP_ASYNC16(p + 24576 + sw, vl_g + go);
        }
    };

    // prologue: Q tile (hi/lo) + mask bits + KV chunk 0
    #pragma unroll
    for (int i = 0; i < 4; i++) {
        int row = rowb + 32 * i;
        uint32_t sw = (uint32_t)(row * 128) + (uint32_t)(((seg ^ (row & 7)) << 4));
        size_t go = (rbase + t0 + row) * 1024 + fcol + seg * 8;
        CP_ASYNC16(sb + FA_QOFF + sw,         qh_g + go);
        CP_ASYNC16(sb + FA_QOFF + 16384 + sw, ql_g + go);
    }
    #pragma unroll
    for (int j = 0; j < 16; j++) {
        int idx = tid + 256 * j;
        int r = idx >> 5, w = idx & 31;
        msk[r * 33 + w] = mbits[((size_t)b * 1024 + t0 + r) * 32 + w];
    }
    load_kv(0, 0); CP_COMMIT();

    float m0 = -INFINITY, m1 = -INFINITY, l0 = 0.f, l1 = 0.f;
    float o[8][4];
    #pragma unroll
    for (int j = 0; j < 8; j++)
        #pragma unroll
        for (int e = 0; e < 4; e++) o[j][e] = 0.f;
    const int lr0 = wt0 + (lane >> 2);

    #pragma unroll 1
    for (int c = 0; c < 16; c++) {
        if (c < 15) { load_kv(c + 1, (c + 1) & 1); CP_COMMIT(); CP_WAIT(1); }
        else        { CP_WAIT(0); }
        __syncthreads();
        const uint32_t kv = sb + (c & 1) * FA_KVBUF;

        // Q fragments (reloaded per chunk to cap register pressure)
        uint32_t qfh[4][4], qfl[4][4];
        {
            const int rA = wt0 + (lane & 15), cg = lane >> 4;
            #pragma unroll
            for (int ks = 0; ks < 4; ks++) {
                uint32_t off = (uint32_t)(rA * 128) + (uint32_t)((((ks*2+cg)) ^ (rA & 7)) << 4);
                LDSM4(qfh[ks][0], qfh[ks][1], qfh[ks][2], qfh[ks][3], sb + FA_QOFF + off);
                LDSM4(qfl[ks][0], qfl[ks][1], qfl[ks][2], qfl[ks][3], sb + FA_QOFF + 16384 + off);
            }
        }

        // ---- S = Q K^T (64 columns) ----
        float s[8][4];
        #pragma unroll
        for (int i = 0; i < 8; i++)
            #pragma unroll
            for (int e = 0; e < 4; e++) s[i][e] = 0.f;
        #pragma unroll
        for (int np = 0; np < 4; np++) {
            const int rB = np * 16 + (lane & 7) + ((lane >> 4) & 1) * 8;
            const int cg = (lane >> 3) & 1;
            #pragma unroll
            for (int ks = 0; ks < 4; ks++) {
                uint32_t off = (uint32_t)(rB * 128) + (uint32_t)((((ks*2+cg)) ^ (rB & 7)) << 4);
                uint32_t k4[4], kl4[4];
                LDSM4(k4[0], k4[1], k4[2], k4[3], kv + off);
                LDSM4(kl4[0], kl4[1], kl4[2], kl4[3], kv + 8192 + off);
                MMA16816(s[2*np],   qfh[ks][0],qfh[ks][1],qfh[ks][2],qfh[ks][3], k4[0], k4[1]);
                MMA16816(s[2*np],   qfh[ks][0],qfh[ks][1],qfh[ks][2],qfh[ks][3], kl4[0], kl4[1]);
                MMA16816(s[2*np],   qfl[ks][0],qfl[ks][1],qfl[ks][2],qfl[ks][3], k4[0], k4[1]);
                MMA16816(s[2*np+1], qfh[ks][0],qfh[ks][1],qfh[ks][2],qfh[ks][3], k4[2], k4[3]);
                MMA16816(s[2*np+1], qfh[ks][0],qfh[ks][1],qfh[ks][2],qfh[ks][3], kl4[2], kl4[3]);
                MMA16816(s[2*np+1], qfl[ks][0],qfl[ks][1],qfl[ks][2],qfl[ks][3], k4[2], k4[3]);
            }
        }

        // ---- mask + online softmax ----
        float cm0 = -3.4e38f, cm1 = -3.4e38f;
        #pragma unroll
        for (int nt = 0; nt < 8; nt++) {
            const int bp = (8 * nt + 2 * (lane & 3)) & 31;
            const uint32_t wa = msk[lr0 * 33 + c * 2 + (nt >> 2)];
            const uint32_t wb = msk[(lr0 + 8) * 33 + c * 2 + (nt >> 2)];
            if (!((wa >> bp) & 1))       s[nt][0] = -1e9f;
            if (!((wa >> (bp + 1)) & 1)) s[nt][1] = -1e9f;
            if (!((wb >> bp) & 1))       s[nt][2] = -1e9f;
            if (!((wb >> (bp + 1)) & 1)) s[nt][3] = -1e9f;
            cm0 = fmaxf(cm0, fmaxf(s[nt][0], s[nt][1]));
            cm1 = fmaxf(cm1, fmaxf(s[nt][2], s[nt][3]));
        }
        cm0 = fmaxf(cm0, __shfl_xor_sync(0xffffffffu, cm0, 1));
        cm0 = fmaxf(cm0, __shfl_xor_sync(0xffffffffu, cm0, 2));
        cm1 = fmaxf(cm1, __shfl_xor_sync(0xffffffffu, cm1, 1));
        cm1 = fmaxf(cm1, __shfl_xor_sync(0xffffffffu, cm1, 2));
        float mn0 = fmaxf(m0, cm0), mn1 = fmaxf(m1, cm1);
        float sc0 = __expf(m0 - mn0), sc1 = __expf(m1 - mn1);
        m0 = mn0; m1 = mn1;
        float rs0 = 0.f, rs1 = 0.f;
        #pragma unroll
        for (int nt = 0; nt < 8; nt++) {
            s[nt][0] = __expf(s[nt][0] - mn0); s[nt][1] = __expf(s[nt][1] - mn0);
            s[nt][2] = __expf(s[nt][2] - mn1); s[nt][3] = __expf(s[nt][3] - mn1);
            rs0 += s[nt][0] + s[nt][1];
            rs1 += s[nt][2] + s[nt][3];
        }
        l0 = l0 * sc0 + rs0; l1 = l1 * sc1 + rs1;
        #pragma unroll
        for (int j = 0; j < 8; j++) {
            o[j][0] *= sc0; o[j][1] *= sc0; o[j][2] *= sc1; o[j][3] *= sc1;
        }

        // ---- O += P V ----
        #pragma unroll
        for (int ks = 0; ks < 4; ks++) {
            uint32_t ph[4], pl[4];
            pack_hilo(s[2*ks][0],   s[2*ks][1],   ph[0], pl[0]);
            pack_hilo(s[2*ks][2],   s[2*ks][3],   ph[1], pl[1]);
            pack_hilo(s[2*ks+1][0], s[2*ks+1][1], ph[2], pl[2]);
            pack_hilo(s[2*ks+1][2], s[2*ks+1][3], ph[3], pl[3]);
            const int vrow = ks * 16 + (lane & 7) + 8 * ((lane >> 3) & 1);
            #pragma unroll
            for (int ds = 0; ds < 4; ds++) {
                uint32_t off = (uint32_t)(vrow * 128) +
                               (uint32_t)((((ds*2 + (lane >> 4))) ^ (vrow & 7)) << 4);
                uint32_t v4[4], vl4[4];
                LDSM4T(v4[0], v4[1], v4[2], v4[3], kv + 16384 + off);
                LDSM4T(vl4[0], vl4[1], vl4[2], vl4[3], kv + 24576 + off);
                MMA16816(o[2*ds],   ph[0],ph[1],ph[2],ph[3], v4[0], v4[1]);
                MMA16816(o[2*ds],   ph[0],ph[1],ph[2],ph[3], vl4[0], vl4[1]);
                MMA16816(o[2*ds],   pl[0],pl[1],pl[2],pl[3], v4[0], v4[1]);
                MMA16816(o[2*ds+1], ph[0],ph[1],ph[2],ph[3], v4[2], v4[3]);
                MMA16816(o[2*ds+1], ph[0],ph[1],ph[2],ph[3], vl4[2], vl4[3]);
                MMA16816(o[2*ds+1], pl[0],pl[1],pl[2],pl[3], v4[2], v4[3]);
            }
        }
        __syncthreads();
    }

    l0 += __shfl_xor_sync(0xffffffffu, l0, 1);
    l0 += __shfl_xor_sync(0xffffffffu, l0, 2);
    l1 += __shfl_xor_sync(0xffffffffu, l1, 1);
    l1 += __shfl_xor_sync(0xffffffffu, l1, 2);
    const float i0 = 1.f / l0, i1 = 1.f / l1;
    size_t ra = (rbase + t0 + lr0) * 1024 + fcol + 2 * (lane & 3);
    size_t rb2 = ra + 8 * 1024;
    #pragma unroll
    for (int j = 0; j < 8; j++) {
        uint32_t h0, lo0, h1, lo1;
        pack_hilo(o[j][0] * i0, o[j][1] * i0, h0, lo0);
        pack_hilo(o[j][2] * i1, o[j][3] * i1, h1, lo1);
        *(uint32_t*)(aoh_g + ra + 8*j)  = h0;
        *(uint32_t*)(aol_g + ra + 8*j)  = lo0;
        *(uint32_t*)(aoh_g + rb2 + 8*j) = h1;
        *(uint32_t*)(aol_g + rb2 + 8*j) = lo1;
    }
}

// ---------------- projection GEMM ----------------
#define PROJ_SMEM_BYTES (2 * 4 * 16384)

__global__ __launch_bounds__(256, 1)
void proj_mma_kernel(const __nv_bfloat16* __restrict__ ah_g, const __nv_bfloat16* __restrict__ al_g,
                     const __nv_bfloat16* __restrict__ wh_g, const __nv_bfloat16* __restrict__ wl_g,
                     const float* __restrict__ bo, float* __restrict__ out) {
    extern __shared__ char dsm[];
    const int tid = threadIdx.x, wid = tid >> 5, lane = tid & 31;
    const int m0 = blockIdx.x * 128, n0 = blockIdx.y * 128;
    const uint32_t sbase = smem_to_u32(dsm);
    const int rowb = tid >> 3, seg = tid & 7;

    auto load_chunk = [&](int c, int buf) {
        const int ci0 = c << 6;
        const uint32_t sb = sbase + buf * 65536;
        #pragma unroll
        for (int i = 0; i < 4; i++) {
            int row = rowb + 32 * i;
            uint32_t sw = (uint32_t)(row * 128) + (uint32_t)(((seg ^ (row & 7)) << 4));
            size_t ao = (size_t)(m0 + row) * 1024 + ci0 + seg * 8;
            size_t wo = (size_t)(n0 + row) * 1024 + ci0 + seg * 8;
            CP_ASYNC16(sb + sw,         ah_g + ao);
            CP_ASYNC16(sb + 16384 + sw, al_g + ao);
            CP_ASYNC16(sb + 32768 + sw, wh_g + wo);
            CP_ASYNC16(sb + 49152 + sw, wl_g + wo);
        }
    };

    const int wm = (wid & 1) * 64, wn = (wid >> 1) * 32;
    int rowA[4], xorA[4];
    #pragma unroll
    for (int mt = 0; mt < 4; mt++) { rowA[mt] = wm + mt * 16 + (lane & 15); xorA[mt] = rowA[mt] & 7; }
    const int cgA = lane >> 4;
    int rowB[2], xorB[2];
    #pragma unroll
    for (int np = 0; np < 2; np++) {
        rowB[np] = wn + np * 16 + (lane & 7) + ((lane >> 4) & 1) * 8;
        xorB[np] = rowB[np] & 7;
    }
    const int cgB = (lane >> 3) & 1;

    float acc[4][4][4];
    #pragma unroll
    for (int mt = 0; mt < 4; mt++)
        #pragma unroll
        for (int nt = 0; nt < 4; nt++)
            #pragma unroll
            for (int e = 0; e < 4; e++) acc[mt][nt][e] = 0.f;

    load_chunk(0, 0); CP_COMMIT();
    for (int c = 0; c < 16; ++c) {
        const int buf = c & 1;
        if (c < 15) { load_chunk(c + 1, (c + 1) & 1); CP_COMMIT(); CP_WAIT(1); }
        else        { CP_WAIT(0); }
        __syncthreads();
        const uint32_t sb = sbase + buf * 65536;
        const uint32_t aHi = sb, aLo = sb + 16384, bHi = sb + 32768, bLo = sb + 49152;
        #pragma unroll
        for (int ks = 0; ks < 4; ks++) {
            uint32_t ah[4][4], al[4][4], bh2[2][4], bl2[2][4];
            #pragma unroll
            for (int mt = 0; mt < 4; mt++) {
                uint32_t off = (uint32_t)(rowA[mt] * 128) + (uint32_t)(((ks*2+cgA) ^ xorA[mt]) << 4);
                LDSM4(ah[mt][0], ah[mt][1], ah[mt][2], ah[mt][3], aHi + off);
                LDSM4(al[mt][0], al[mt][1], al[mt][2], al[mt][3], aLo + off);
            }
            #pragma unroll
            for (int np = 0; np < 2; np++) {
                uint32_t off = (uint32_t)(rowB[np] * 128) + (uint32_t)(((ks*2+cgB) ^ xorB[np]) << 4);
                LDSM4(bh2[np][0], bh2[np][1], bh2[np][2], bh2[np][3], bHi + off);
                LDSM4(bl2[np][0], bl2[np][1], bl2[np][2], bl2[np][3], bLo + off);
            }
            #pragma unroll
            for (int mt = 0; mt < 4; mt++)
                #pragma unroll
                for (int nt = 0; nt < 4; nt++) {
                    const int np = nt >> 1, h = (nt & 1) * 2;
                    MMA16816(acc[mt][nt], ah[mt][0],ah[mt][1],ah[mt][2],ah[mt][3], bh2[np][h], bh2[np][h+1]);
                    MMA16816(acc[mt][nt], ah[mt][0],ah[mt][1],ah[mt][2],ah[mt][3], bl2[np][h], bl2[np][h+1]);
                    MMA16816(acc[mt][nt], al[mt][0],al[mt][1],al[mt][2],al[mt][3], bh2[np][h], bh2[np][h+1]);
                }
        }
        __syncthreads();
    }

    #pragma unroll
    for (int mt = 0; mt < 4; mt++) {
        const int ma = m0 + wm + mt * 16 + (lane >> 2);
        const int mb2 = ma + 8;
        #pragma unroll
        for (int nt = 0; nt < 4; nt++) {
            const int n = n0 + wn + nt * 8 + 2 * (lane & 3);
            const float b0 = bo[n], b1 = bo[n + 1];
            *(float2*)(out + (size_t)ma * 1024 + n)  = make_float2(acc[mt][nt][0] + b0, acc[mt][nt][1] + b1);
            *(float2*)(out + (size_t)mb2 * 1024 + n) = make_float2(acc[mt][nt][2] + b0, acc[mt][nt][3] + b1);
        }
    }
}

// ---------------- kernel_launch ----------------
extern "C" void kernel_launch(void* const* d_in, const int* in_sizes, int n_in,
                              void* d_out, int out_size)
{
    (void)in_sizes; (void)n_in; (void)out_size;
    const float* q   = (const float*)d_in[0];
    const float* k   = (const float*)d_in[1];
    const float* v   = (const float*)d_in[2];
    const float* Wq  = (const float*)d_in[3];
    const float* bq  = (const float*)d_in[4];
    const float* Wk  = (const float*)d_in[5];
    const float* bk  = (const float*)d_in[6];
    const float* Wv  = (const float*)d_in[7];
    const float* bv  = (const float*)d_in[8];
    const float* Wo  = (const float*)d_in[9];
    const float* bo  = (const float*)d_in[10];
    const int*  mask = (const int*) d_in[11];
    float* out = (float*)d_out;

    __nv_bfloat16 *uwh, *uwl, *vwh, *vwl, *qh, *ql, *kh, *kl, *vh, *vl, *aoh, *aol, *woh, *wol;
    float* mw;
    uint32_t* mb;
    cudaGetSymbolAddress((void**)&uwh, g_uwh);   cudaGetSymbolAddress((void**)&uwl, g_uwl);
    cudaGetSymbolAddress((void**)&vwh, g_vwh);   cudaGetSymbolAddress((void**)&vwl, g_vwl);
    cudaGetSymbolAddress((void**)&mw, g_mw);
    cudaGetSymbolAddress((void**)&qh, g_qh);     cudaGetSymbolAddress((void**)&ql, g_ql);
    cudaGetSymbolAddress((void**)&kh, g_kh);     cudaGetSymbolAddress((void**)&kl, g_kl);
    cudaGetSymbolAddress((void**)&vh, g_vh);     cudaGetSymbolAddress((void**)&vl, g_vl);
    cudaGetSymbolAddress((void**)&aoh, g_aoh);   cudaGetSymbolAddress((void**)&aol, g_aol);
    cudaGetSymbolAddress((void**)&woh, g_woh);   cudaGetSymbolAddress((void**)&wol, g_wol);
    cudaGetSymbolAddress((void**)&mb, g_mb);

    cudaFuncSetAttribute(wino_gemm_kernel, cudaFuncAttributeMaxDynamicSharedMemorySize, GEMM_SMEM_BYTES);
    cudaFuncSetAttribute(flash_kernel,     cudaFuncAttributeMaxDynamicSharedMemorySize, FA_SMEM_BYTES);
    cudaFuncSetAttribute(proj_mma_kernel,  cudaFuncAttributeMaxDynamicSharedMemorySize, PROJ_SMEM_BYTES);

    prep_kernel<<<55296, 256>>>(q, k, v, Wq, Wk, Wv, Wo, mask,
                                vwh, vwl, uwh, uwl, woh, wol, mb);

    wino_gemm_kernel<<<dim3(8, 4, 108), 256, GEMM_SMEM_BYTES>>>(uwh, uwl, vwh, vwl, mw);
    wino_out_kernel<<<6144, 256>>>(mw, bq, bk, bv, qh, ql, kh, kl, vh, vl);

    flash_kernel<<<dim3(8, 128), 256, FA_SMEM_BYTES>>>(
        qh, ql, kh, kl, vh, vl, mb, aoh, aol);

    proj_mma_kernel<<<dim3(64, 8), 256, PROJ_SMEM_BYTES>>>(aoh, aol, woh, wol, bo, out);
}

// round 16
// speedup vs baseline: 1.0189x; 1.0189x over previous
#include <cuda_runtime.h>
#include <cuda_bf16.h>
#include <cstdint>
#include <math.h>

__device__ __forceinline__ uint32_t smem_to_u32(const void* p) {
    uint32_t a;
    asm("{ .reg .u64 t; cvta.to.shared.u64 t, %1; cvt.u32.u64 %0, t; }" : "=r"(a) : "l"(p));
    return a;
}
#define CP_ASYNC16(d, s) asm volatile("cp.async.cg.shared.global [%0], [%1], 16;" :: "r"(d), "l"(s))
#define CP_COMMIT() asm volatile("cp.async.commit_group;")
#define CP_WAIT(N)  asm volatile("cp.async.wait_group %0;" :: "n"(N))
#define LDSM4(R0,R1,R2,R3,A) \
    asm volatile("ldmatrix.sync.aligned.m8n8.x4.shared.b16 {%0,%1,%2,%3}, [%4];" \
        : "=r"(R0),"=r"(R1),"=r"(R2),"=r"(R3) : "r"(A))
#define LDSM4T(R0,R1,R2,R3,A) \
    asm volatile("ldmatrix.sync.aligned.m8n8.x4.trans.shared.b16 {%0,%1,%2,%3}, [%4];" \
        : "=r"(R0),"=r"(R1),"=r"(R2),"=r"(R3) : "r"(A))
#define MMA16816(D,A0,A1,A2,A3,B0,B1) \
    asm volatile("mma.sync.aligned.m16n8k16.row.col.f32.bf16.bf16.f32 " \
        "{%0,%1,%2,%3}, {%4,%5,%6,%7}, {%8,%9}, {%0,%1,%2,%3};" \
        : "+f"((D)[0]),"+f"((D)[1]),"+f"((D)[2]),"+f"((D)[3]) \
        : "r"(A0),"r"(A1),"r"(A2),"r"(A3),"r"(B0),"r"(B1))

__device__ __forceinline__ void pack_hilo(float v0, float v1, uint32_t& hi, uint32_t& lo) {
    uint32_t h;
    asm("cvt.rn.bf16x2.f32 %0, %1, %2;" : "=r"(h) : "f"(v1), "f"(v0));
    float l0 = v0 - __uint_as_float(h << 16);
    float l1 = v1 - __uint_as_float(h & 0xffff0000u);
    asm("cvt.rn.bf16x2.f32 %0, %1, %2;" : "=r"(lo) : "f"(l1), "f"(l0));
    hi = h;
}

// ---------------- scratch ----------------
#define QKV_ELEMS (8u * 1024u * 1024u)
#define UW_ELEMS  (108ull * 1024u * 1024u)
#define VW_ELEMS  (108ull * 512u * 1024u)
__device__ __align__(128) __nv_bfloat16 g_uwh[UW_ELEMS], g_uwl[UW_ELEMS];
__device__ __align__(128) __nv_bfloat16 g_vwh[VW_ELEMS], g_vwl[VW_ELEMS];
__device__ __align__(128) float g_mw[108ull * 1024u * 512u];
__device__ __align__(128) __nv_bfloat16 g_qh[QKV_ELEMS], g_ql[QKV_ELEMS];
__device__ __align__(128) __nv_bfloat16 g_kh[QKV_ELEMS], g_kl[QKV_ELEMS];
__device__ __align__(128) __nv_bfloat16 g_vh[QKV_ELEMS], g_vl[QKV_ELEMS];
__device__ __align__(128) __nv_bfloat16 g_aoh[QKV_ELEMS], g_aol[QKV_ELEMS];
__device__ __align__(128) __nv_bfloat16 g_woh[1024u*1024u], g_wol[1024u*1024u];
__device__ __align__(128) uint32_t g_mb[8u * 1024u * 32u];

// ---------------- Winograd transform helpers ----------------
__device__ __forceinline__ void gtrans(float a, float b, float d, float* y) {
    const float s6 = 1.f / 6.f, s12 = 1.f / 12.f, s24 = 1.f / 24.f;
    y[0] = 0.25f * a;
    y[1] = -(a + b + d) * s6;
    y[2] = (-a + b - d) * s6;
    y[3] = a * s24 + b * s12 + d * s6;
    y[4] = a * s24 - b * s12 + d * s6;
    y[5] = d;
}
__device__ __forceinline__ void btrans(const float* x, float* y) {
    y[0] = 4.f * x[0] - 5.f * x[2] + x[4];
    y[1] = -4.f * x[1] - 4.f * x[2] + x[3] + x[4];
    y[2] = 4.f * x[1] - 4.f * x[2] - x[3] + x[4];
    y[3] = -2.f * x[1] - x[2] + 2.f * x[3] + x[4];
    y[4] = 2.f * x[1] - x[2] - 2.f * x[3] + x[4];
    y[5] = 4.f * x[1] - 5.f * x[3] + x[5];
}
__device__ __forceinline__ void atrans(const float* x, float* y) {
    y[0] = x[0] + x[1] + x[2] + x[3] + x[4];
    y[1] = x[1] - x[2] + 2.f * x[3] - 2.f * x[4];
    y[2] = x[1] + x[2] + 4.f * x[3] + 4.f * x[4];
    y[3] = x[1] - x[2] + 8.f * x[3] - 8.f * x[4] + x[5];
}

// ====================================================================
// Merged prep kernel
// ====================================================================
__global__ __launch_bounds__(256)
void prep_kernel(const float* __restrict__ q, const float* __restrict__ k,
                 const float* __restrict__ v,
                 const float* __restrict__ Wq, const float* __restrict__ Wk,
                 const float* __restrict__ Wv, const float* __restrict__ Wo,
                 const int* __restrict__ mask,
                 __nv_bfloat16* __restrict__ vwh, __nv_bfloat16* __restrict__ vwl,
                 __nv_bfloat16* __restrict__ uh,  __nv_bfloat16* __restrict__ ul,
                 __nv_bfloat16* __restrict__ woh, __nv_bfloat16* __restrict__ wol,
                 uint32_t* __restrict__ mb) {
    __shared__ float xs[6][32][34];
    const int bx = blockIdx.x, tid = threadIdx.x;

    if (bx < 6144) {
        const int ty = bx & 7, ci0 = ((bx >> 3) & 31) * 32;
        const int zz = bx >> 8;
        const int conv = zz >> 3, b = zz & 7;
        const float* x = conv == 0 ? q : (conv == 1 ? k : v);
        for (int l = tid; l < 6 * 32 * 34; l += 256) {
            int u = l / 1088;
            int rem = l - u * 1088;
            int ci = rem / 34, cc = rem - ci * 34;
            int gr = 4 * ty - 1 + u, gc = cc - 1;
            float val = 0.f;
            if ((unsigned)gr < 32u && (unsigned)gc < 32u)
                val = x[((size_t)(b * 1024 + ci0 + ci)) * 1024 + gr * 32 + gc];
            xs[u][ci][cc] = val;
        }
        __syncthreads();
        const int tx = tid >> 5, ci = tid & 31;
        float d[6][6];
        #pragma unroll
        for (int u = 0; u < 6; u++)
            #pragma unroll
            for (int vv = 0; vv < 6; vv++) d[u][vv] = xs[u][ci][4 * tx + vv];
        float t1[6][6];
        #pragma unroll
        for (int vv = 0; vv < 6; vv++) {
            float col[6] = {d[0][vv], d[1][vv], d[2][vv], d[3][vv], d[4][vv], d[5][vv]};
            float y[6];
            btrans(col, y);
            #pragma unroll
            for (int u = 0; u < 6; u++) t1[u][vv] = y[u];
        }
        const size_t tile = (size_t)b * 64 + ty * 8 + tx;
        #pragma unroll
        for (int u = 0; u < 6; u++) {
            float y[6];
            btrans(t1[u], y);
            #pragma unroll
            for (int vv = 0; vv < 6; vv++) {
                int kk = u * 6 + vv;
                size_t o = ((size_t)(conv * 36 + kk) * 512 + tile) * 1024 + ci0 + ci;
                __nv_bfloat16 h = __float2bfloat16(y[vv]);
                vwh[o] = h;
                vwl[o] = __float2bfloat16(y[vv] - __bfloat162float(h));
            }
        }
    } else if (bx < 18432) {
        int i = (bx - 6144) * 256 + tid;
        int conv = i >> 20;
        int co = (i >> 10) & 1023, ci = i & 1023;
        const float* W = conv == 0 ? Wq : (conv == 1 ? Wk : Wv);
        const float* g = W + ((size_t)co * 1024 + ci) * 9;
        float t[6][3];
        #pragma unroll
        for (int c = 0; c < 3; c++) {
            float col[6];
            gtrans(g[c], g[3 + c], g[6 + c], col);
            #pragma unroll
            for (int u = 0; u < 6; u++) t[u][c] = col[u];
        }
        #pragma unroll
        for (int u = 0; u < 6; u++) {
            float U[6];
            gtrans(t[u][0], t[u][1], t[u][2], U);
            #pragma unroll
            for (int vv = 0; vv < 6; vv++) {
                int kk = u * 6 + vv;
                size_t o = (((size_t)(conv * 36 + kk)) << 20) + ((size_t)co << 10) + ci;
                __nv_bfloat16 h = __float2bfloat16(U[vv]);
                uh[o] = h;
                ul[o] = __float2bfloat16(U[vv] - __bfloat162float(h));
            }
        }
    } else if (bx < 22528) {
        int i = (bx - 18432) * 256 + tid;
        float w = Wo[i];
        __nv_bfloat16 h = __float2bfloat16(w);
        woh[i] = h;
        wol[i] = __float2bfloat16(w - __bfloat162float(h));
    } else {
        int idx = (bx - 22528) * 256 + tid;
        uint32_t word = __ballot_sync(0xffffffffu, mask[idx] != 0);
        if ((tid & 31) == 0) mb[idx >> 5] = word;
    }
}

// ====================================================================
// Winograd batched GEMM: M[g] = U[g] * V[g]^T.
// 128co x 64tile tile, 2-stage, 96KB smem -> 2 CTAs/SM.
// Buffer: Ahi 16K | Alo 16K | Bhi 8K | Blo 8K  (stride 49152)
// ====================================================================
#define GEMM_SMEM_BYTES (2 * 49152)

__global__ __launch_bounds__(256, 2)
void wino_gemm_kernel(const __nv_bfloat16* __restrict__ uh, const __nv_bfloat16* __restrict__ ul,
                      const __nv_bfloat16* __restrict__ vwh, const __nv_bfloat16* __restrict__ vwl,
                      float* __restrict__ mw) {
    extern __shared__ char dsm[];
    const int tid = threadIdx.x, wid = tid >> 5, lane = tid & 31;
    const int m0 = blockIdx.x * 128, n0 = blockIdx.y * 64, gidx = blockIdx.z;
    const __nv_bfloat16* ah_g = uh  + ((size_t)gidx << 20);
    const __nv_bfloat16* al_g = ul  + ((size_t)gidx << 20);
    const __nv_bfloat16* bh_g = vwh + ((size_t)gidx << 19);
    const __nv_bfloat16* bl_g = vwl + ((size_t)gidx << 19);
    const uint32_t sbase = smem_to_u32(dsm);
    const int rowb = tid >> 3, seg = tid & 7;

    auto load_chunk = [&](int c, int buf) {
        const int ci0 = c << 6;
        const uint32_t sb = sbase + buf * 49152;
        #pragma unroll
        for (int i = 0; i < 4; i++) {
            int row = rowb + 32 * i;
            uint32_t sw = (uint32_t)(row * 128) + (uint32_t)(((seg ^ (row & 7)) << 4));
            size_t ao = (size_t)(m0 + row) * 1024 + ci0 + seg * 8;
            CP_ASYNC16(sb + sw,         ah_g + ao);
            CP_ASYNC16(sb + 16384 + sw, al_g + ao);
            if (i < 2) {
                size_t bo = (size_t)(n0 + row) * 1024 + ci0 + seg * 8;
                CP_ASYNC16(sb + 32768 + sw, bh_g + bo);
                CP_ASYNC16(sb + 40960 + sw, bl_g + bo);
            }
        }
    };

    // 8 warps: 4 m-subtiles of 32, 2 n-subtiles of 32
    const int wm = (wid & 3) * 32, wn = (wid >> 2) * 32;
    int rowA[2], xorA[2];
    #pragma unroll
    for (int mt = 0; mt < 2; mt++) { rowA[mt] = wm + mt * 16 + (lane & 15); xorA[mt] = rowA[mt] & 7; }
    const int cgA = lane >> 4;
    int rowB[2], xorB[2];
    #pragma unroll
    for (int np = 0; np < 2; np++) {
        rowB[np] = wn + np * 16 + (lane & 7) + ((lane >> 4) & 1) * 8;
        xorB[np] = rowB[np] & 7;
    }
    const int cgB = (lane >> 3) & 1;

    float acc[2][4][4];
    #pragma unroll
    for (int mt = 0; mt < 2; mt++)
        #pragma unroll
        for (int nt = 0; nt < 4; nt++)
            #pragma unroll
            for (int e = 0; e < 4; e++) acc[mt][nt][e] = 0.f;

    load_chunk(0, 0); CP_COMMIT();
    for (int c = 0; c < 16; ++c) {
        const int buf = c & 1;
        if (c < 15) { load_chunk(c + 1, (c + 1) & 1); CP_COMMIT(); CP_WAIT(1); }
        else        { CP_WAIT(0); }
        __syncthreads();
        const uint32_t sb = sbase + buf * 49152;
        const uint32_t aHi = sb, aLo = sb + 16384, bHi = sb + 32768, bLo = sb + 40960;
        #pragma unroll
        for (int ks = 0; ks < 4; ks++) {
            uint32_t ah[2][4], al[2][4], bh2[2][4], bl2[2][4];
            #pragma unroll
            for (int mt = 0; mt < 2; mt++) {
                uint32_t off = (uint32_t)(rowA[mt] * 128) + (uint32_t)(((ks*2+cgA) ^ xorA[mt]) << 4);
                LDSM4(ah[mt][0], ah[mt][1], ah[mt][2], ah[mt][3], aHi + off);
                LDSM4(al[mt][0], al[mt][1], al[mt][2], al[mt][3], aLo + off);
            }
            #pragma unroll
            for (int np = 0; np < 2; np++) {
                uint32_t off = (uint32_t)(rowB[np] * 128) + (uint32_t)(((ks*2+cgB) ^ xorB[np]) << 4);
                LDSM4(bh2[np][0], bh2[np][1], bh2[np][2], bh2[np][3], bHi + off);
                LDSM4(bl2[np][0], bl2[np][1], bl2[np][2], bl2[np][3], bLo + off);
            }
            #pragma unroll
            for (int mt = 0; mt < 2; mt++)
                #pragma unroll
                for (int nt = 0; nt < 4; nt++) {
                    const int np = nt >> 1, h = (nt & 1) * 2;
                    MMA16816(acc[mt][nt], ah[mt][0],ah[mt][1],ah[mt][2],ah[mt][3], bh2[np][h], bh2[np][h+1]);
                    MMA16816(acc[mt][nt], ah[mt][0],ah[mt][1],ah[mt][2],ah[mt][3], bl2[np][h], bl2[np][h+1]);
                    MMA16816(acc[mt][nt], al[mt][0],al[mt][1],al[mt][2],al[mt][3], bh2[np][h], bh2[np][h+1]);
                }
        }
        __syncthreads();
    }

    float* outp = mw + (size_t)gidx * 1024 * 512;
    #pragma unroll
    for (int mt = 0; mt < 2; mt++) {
        const int ma = m0 + wm + mt * 16 + (lane >> 2);
        const int mb2 = ma + 8;
        #pragma unroll
        for (int nt = 0; nt < 4; nt++) {
            const int n = n0 + wn + nt * 8 + 2 * (lane & 3);
            *(float2*)(outp + (size_t)ma  * 512 + n) = make_float2(acc[mt][nt][0], acc[mt][nt][1]);
            *(float2*)(outp + (size_t)mb2 * 512 + n) = make_float2(acc[mt][nt][2], acc[mt][nt][3]);
        }
    }
}

// ---------------- Winograd output transform: Y = A^T M A ----------------
__global__ __launch_bounds__(256)
void wino_out_kernel(const float* __restrict__ mw,
                     const float* __restrict__ bq, const float* __restrict__ bk,
                     const float* __restrict__ bv,
                     __nv_bfloat16* __restrict__ qh, __nv_bfloat16* __restrict__ ql,
                     __nv_bfloat16* __restrict__ kh, __nv_bfloat16* __restrict__ kl,
                     __nv_bfloat16* __restrict__ vh, __nv_bfloat16* __restrict__ vl) {
    const int idx = blockIdx.x * 256 + threadIdx.x;
    const int conv = idx >> 19;
    const int rem = idx & 0x7FFFF;
    const int co = rem >> 9;
    const int tile = rem & 511;

    float M[36];
    #pragma unroll
    for (int kk = 0; kk < 36; kk++)
        M[kk] = mw[(size_t)(conv * 36 + kk) * 524288 + (size_t)co * 512 + tile];

    float t[4][6];
    #pragma unroll
    for (int vv = 0; vv < 6; vv++) {
        float col[6] = {M[vv], M[6 + vv], M[12 + vv], M[18 + vv], M[24 + vv], M[30 + vv]};
        float y[4];
        atrans(col, y);
        #pragma unroll
        for (int r = 0; r < 4; r++) t[r][vv] = y[r];
    }

    __nv_bfloat16 *oh, *ol;
    const float* bias;
    if (conv == 0)      { oh = qh; ol = ql; bias = bq; }
    else if (conv == 1) { oh = kh; ol = kl; bias = bk; }
    else                { oh = vh; ol = vl; bias = bv; }
    const float scale = (conv == 0) ? 0.125f : 1.0f;
    const float bi = bias[co];

    const int b = tile >> 6, tt = tile & 63;
    const int tyy = tt >> 3, txx = tt & 7;
    size_t base = ((size_t)(b * 1024 + co)) * 1024 + (4 * tyy) * 32 + 4 * txx;
    #pragma unroll
    for (int r = 0; r < 4; r++) {
        float y[4];
        atrans(t[r], y);
        uint32_t h0, l0, h1, l1;
        pack_hilo((y[0] + bi) * scale, (y[1] + bi) * scale, h0, l0);
        pack_hilo((y[2] + bi) * scale, (y[3] + bi) * scale, h1, l1);
        size_t o = base + (size_t)r * 32;
        *(uint32_t*)(oh + o)     = h0;
        *(uint32_t*)(oh + o + 2) = h1;
        *(uint32_t*)(ol + o)     = l0;
        *(uint32_t*)(ol + o + 2) = l1;
    }
}

// ====================================================================
// Fused flash attention. KV chunk = 64 rows, 16 chunks, 2 CTAs/SM.
// ====================================================================
#define FA_KVBUF 32768
#define FA_QOFF  (2 * FA_KVBUF)
#define FA_MOFF  (FA_QOFF + 32768)
#define FA_SMEM_BYTES (FA_MOFF + 128 * 33 * 4)

__global__ __launch_bounds__(256, 2)
void flash_kernel(const __nv_bfloat16* __restrict__ qh_g, const __nv_bfloat16* __restrict__ ql_g,
                  const __nv_bfloat16* __restrict__ kh_g, const __nv_bfloat16* __restrict__ kl_g,
                  const __nv_bfloat16* __restrict__ vh_g, const __nv_bfloat16* __restrict__ vl_g,
                  const uint32_t* __restrict__ mbits,
                  __nv_bfloat16* __restrict__ aoh_g, __nv_bfloat16* __restrict__ aol_g) {
    extern __shared__ char dsm[];
    const int tid = threadIdx.x, wid = tid >> 5, lane = tid & 31;
    const int t0 = blockIdx.x * 128, bh = blockIdx.y, b = bh >> 4, h = bh & 15;
    const uint32_t sb = smem_to_u32(dsm);
    uint32_t* msk = (uint32_t*)(dsm + FA_MOFF);
    const int rowb = tid >> 3, seg = tid & 7;
    const size_t rbase = (size_t)b * 1024;
    const int fcol = h * 64, wt0 = wid * 16;

    auto load_kv = [&](int c, int buf) {
        const uint32_t p = sb + buf * FA_KVBUF;
        const int s0 = c * 64;
        #pragma unroll
        for (int i = 0; i < 2; i++) {
            int row = rowb + 32 * i;
            uint32_t sw = (uint32_t)(row * 128) + (uint32_t)(((seg ^ (row & 7)) << 4));
            size_t go = (rbase + s0 + row) * 1024 + fcol + seg * 8;
            CP_ASYNC16(p + sw,         kh_g + go);
            CP_ASYNC16(p + 8192 + sw,  kl_g + go);
            CP_ASYNC16(p + 16384 + sw, vh_g + go);
            CP_ASYNC16(p + 24576 + sw, vl_g + go);
        }
    };

    #pragma unroll
    for (int i = 0; i < 4; i++) {
        int row = rowb + 32 * i;
        uint32_t sw = (uint32_t)(row * 128) + (uint32_t)(((seg ^ (row & 7)) << 4));
        size_t go = (rbase + t0 + row) * 1024 + fcol + seg * 8;
        CP_ASYNC16(sb + FA_QOFF + sw,         qh_g + go);
        CP_ASYNC16(sb + FA_QOFF + 16384 + sw, ql_g + go);
    }
    #pragma unroll
    for (int j = 0; j < 16; j++) {
        int idx = tid + 256 * j;
        int r = idx >> 5, w = idx & 31;
        msk[r * 33 + w] = mbits[((size_t)b * 1024 + t0 + r) * 32 + w];
    }
    load_kv(0, 0); CP_COMMIT();

    float m0 = -INFINITY, m1 = -INFINITY, l0 = 0.f, l1 = 0.f;
    float o[8][4];
    #pragma unroll
    for (int j = 0; j < 8; j++)
        #pragma unroll
        for (int e = 0; e < 4; e++) o[j][e] = 0.f;
    const int lr0 = wt0 + (lane >> 2);

    #pragma unroll 1
    for (int c = 0; c < 16; c++) {
        if (c < 15) { load_kv(c + 1, (c + 1) & 1); CP_COMMIT(); CP_WAIT(1); }
        else        { CP_WAIT(0); }
        __syncthreads();
        const uint32_t kv = sb + (c & 1) * FA_KVBUF;

        uint32_t qfh[4][4], qfl[4][4];
        {
            const int rA = wt0 + (lane & 15), cg = lane >> 4;
            #pragma unroll
            for (int ks = 0; ks < 4; ks++) {
                uint32_t off = (uint32_t)(rA * 128) + (uint32_t)((((ks*2+cg)) ^ (rA & 7)) << 4);
                LDSM4(qfh[ks][0], qfh[ks][1], qfh[ks][2], qfh[ks][3], sb + FA_QOFF + off);
                LDSM4(qfl[ks][0], qfl[ks][1], qfl[ks][2], qfl[ks][3], sb + FA_QOFF + 16384 + off);
            }
        }

        float s[8][4];
        #pragma unroll
        for (int i = 0; i < 8; i++)
            #pragma unroll
            for (int e = 0; e < 4; e++) s[i][e] = 0.f;
        #pragma unroll
        for (int np = 0; np < 4; np++) {
            const int rB = np * 16 + (lane & 7) + ((lane >> 4) & 1) * 8;
            const int cg = (lane >> 3) & 1;
            #pragma unroll
            for (int ks = 0; ks < 4; ks++) {
                uint32_t off = (uint32_t)(rB * 128) + (uint32_t)((((ks*2+cg)) ^ (rB & 7)) << 4);
                uint32_t k4[4], kl4[4];
                LDSM4(k4[0], k4[1], k4[2], k4[3], kv + off);
                LDSM4(kl4[0], kl4[1], kl4[2], kl4[3], kv + 8192 + off);
                MMA16816(s[2*np],   qfh[ks][0],qfh[ks][1],qfh[ks][2],qfh[ks][3], k4[0], k4[1]);
                MMA16816(s[2*np],   qfh[ks][0],qfh[ks][1],qfh[ks][2],qfh[ks][3], kl4[0], kl4[1]);
                MMA16816(s[2*np],   qfl[ks][0],qfl[ks][1],qfl[ks][2],qfl[ks][3], k4[0], k4[1]);
                MMA16816(s[2*np+1], qfh[ks][0],qfh[ks][1],qfh[ks][2],qfh[ks][3], k4[2], k4[3]);
                MMA16816(s[2*np+1], qfh[ks][0],qfh[ks][1],qfh[ks][2],qfh[ks][3], kl4[2], kl4[3]);
                MMA16816(s[2*np+1], qfl[ks][0],qfl[ks][1],qfl[ks][2],qfl[ks][3], k4[2], k4[3]);
            }
        }

        float cm0 = -3.4e38f, cm1 = -3.4e38f;
        #pragma unroll
        for (int nt = 0; nt < 8; nt++) {
            const int bp = (8 * nt + 2 * (lane & 3)) & 31;
            const uint32_t wa = msk[lr0 * 33 + c * 2 + (nt >> 2)];
            const uint32_t wb = msk[(lr0 + 8) * 33 + c * 2 + (nt >> 2)];
            if (!((wa >> bp) & 1))       s[nt][0] = -1e9f;
            if (!((wa >> (bp + 1)) & 1)) s[nt][1] = -1e9f;
            if (!((wb >> bp) & 1))       s[nt][2] = -1e9f;
            if (!((wb >> (bp + 1)) & 1)) s[nt][3] = -1e9f;
            cm0 = fmaxf(cm0, fmaxf(s[nt][0], s[nt][1]));
            cm1 = fmaxf(cm1, fmaxf(s[nt][2], s[nt][3]));
        }
        cm0 = fmaxf(cm0, __shfl_xor_sync(0xffffffffu, cm0, 1));
        cm0 = fmaxf(cm0, __shfl_xor_sync(0xffffffffu, cm0, 2));
        cm1 = fmaxf(cm1, __shfl_xor_sync(0xffffffffu, cm1, 1));
        cm1 = fmaxf(cm1, __shfl_xor_sync(0xffffffffu, cm1, 2));
        float mn0 = fmaxf(m0, cm0), mn1 = fmaxf(m1, cm1);
        float sc0 = __expf(m0 - mn0), sc1 = __expf(m1 - mn1);
        m0 = mn0; m1 = mn1;
        float rs0 = 0.f, rs1 = 0.f;
        #pragma unroll
        for (int nt = 0; nt < 8; nt++) {
            s[nt][0] = __expf(s[nt][0] - mn0); s[nt][1] = __expf(s[nt][1] - mn0);
            s[nt][2] = __expf(s[nt][2] - mn1); s[nt][3] = __expf(s[nt][3] - mn1);
            rs0 += s[nt][0] + s[nt][1];
            rs1 += s[nt][2] + s[nt][3];
        }
        l0 = l0 * sc0 + rs0; l1 = l1 * sc1 + rs1;
        #pragma unroll
        for (int j = 0; j < 8; j++) {
            o[j][0] *= sc0; o[j][1] *= sc0; o[j][2] *= sc1; o[j][3] *= sc1;
        }

        #pragma unroll
        for (int ks = 0; ks < 4; ks++) {
            uint32_t ph[4], pl[4];
            pack_hilo(s[2*ks][0],   s[2*ks][1],   ph[0], pl[0]);
            pack_hilo(s[2*ks][2],   s[2*ks][3],   ph[1], pl[1]);
            pack_hilo(s[2*ks+1][0], s[2*ks+1][1], ph[2], pl[2]);
            pack_hilo(s[2*ks+1][2], s[2*ks+1][3], ph[3], pl[3]);
            const int vrow = ks * 16 + (lane & 7) + 8 * ((lane >> 3) & 1);
            #pragma unroll
            for (int ds = 0; ds < 4; ds++) {
                uint32_t off = (uint32_t)(vrow * 128) +
                               (uint32_t)((((ds*2 + (lane >> 4))) ^ (vrow & 7)) << 4);
                uint32_t v4[4], vl4[4];
                LDSM4T(v4[0], v4[1], v4[2], v4[3], kv + 16384 + off);
                LDSM4T(vl4[0], vl4[1], vl4[2], vl4[3], kv + 24576 + off);
                MMA16816(o[2*ds],   ph[0],ph[1],ph[2],ph[3], v4[0], v4[1]);
                MMA16816(o[2*ds],   ph[0],ph[1],ph[2],ph[3], vl4[0], vl4[1]);
                MMA16816(o[2*ds],   pl[0],pl[1],pl[2],pl[3], v4[0], v4[1]);
                MMA16816(o[2*ds+1], ph[0],ph[1],ph[2],ph[3], v4[2], v4[3]);
                MMA16816(o[2*ds+1], ph[0],ph[1],ph[2],ph[3], vl4[2], vl4[3]);
                MMA16816(o[2*ds+1], pl[0],pl[1],pl[2],pl[3], v4[2], v4[3]);
            }
        }
        __syncthreads();
    }

    l0 += __shfl_xor_sync(0xffffffffu, l0, 1);
    l0 += __shfl_xor_sync(0xffffffffu, l0, 2);
    l1 += __shfl_xor_sync(0xffffffffu, l1, 1);
    l1 += __shfl_xor_sync(0xffffffffu, l1, 2);
    const float i0 = 1.f / l0, i1 = 1.f / l1;
    size_t ra = (rbase + t0 + lr0) * 1024 + fcol + 2 * (lane & 3);
    size_t rb2 = ra + 8 * 1024;
    #pragma unroll
    for (int j = 0; j < 8; j++) {
        uint32_t h0, lo0, h1, lo1;
        pack_hilo(o[j][0] * i0, o[j][1] * i0, h0, lo0);
        pack_hilo(o[j][2] * i1, o[j][3] * i1, h1, lo1);
        *(uint32_t*)(aoh_g + ra + 8*j)  = h0;
        *(uint32_t*)(aol_g + ra + 8*j)  = lo0;
        *(uint32_t*)(aoh_g + rb2 + 8*j) = h1;
        *(uint32_t*)(aol_g + rb2 + 8*j) = lo1;
    }
}

// ====================================================================
// Projection GEMM: 128 x 64 tile, 2-stage, 96KB, 2 CTAs/SM.
// ====================================================================
__global__ __launch_bounds__(256, 2)
void proj_mma_kernel(const __nv_bfloat16* __restrict__ ah_g, const __nv_bfloat16* __restrict__ al_g,
                     const __nv_bfloat16* __restrict__ wh_g, const __nv_bfloat16* __restrict__ wl_g,
                     const float* __restrict__ bo, float* __restrict__ out) {
    extern __shared__ char dsm[];
    const int tid = threadIdx.x, wid = tid >> 5, lane = tid & 31;
    const int m0 = blockIdx.x * 128, n0 = blockIdx.y * 64;
    const uint32_t sbase = smem_to_u32(dsm);
    const int rowb = tid >> 3, seg = tid & 7;

    auto load_chunk = [&](int c, int buf) {
        const int ci0 = c << 6;
        const uint32_t sb = sbase + buf * 49152;
        #pragma unroll
        for (int i = 0; i < 4; i++) {
            int row = rowb + 32 * i;
            uint32_t sw = (uint32_t)(row * 128) + (uint32_t)(((seg ^ (row & 7)) << 4));
            size_t ao = (size_t)(m0 + row) * 1024 + ci0 + seg * 8;
            CP_ASYNC16(sb + sw,         ah_g + ao);
            CP_ASYNC16(sb + 16384 + sw, al_g + ao);
            if (i < 2) {
                size_t wo = (size_t)(n0 + row) * 1024 + ci0 + seg * 8;
                CP_ASYNC16(sb + 32768 + sw, wh_g + wo);
                CP_ASYNC16(sb + 40960 + sw, wl_g + wo);
            }
        }
    };

    const int wm = (wid & 3) * 32, wn = (wid >> 2) * 32;
    int rowA[2], xorA[2];
    #pragma unroll
    for (int mt = 0; mt < 2; mt++) { rowA[mt] = wm + mt * 16 + (lane & 15); xorA[mt] = rowA[mt] & 7; }
    const int cgA = lane >> 4;
    int rowB[2], xorB[2];
    #pragma unroll
    for (int np = 0; np < 2; np++) {
        rowB[np] = wn + np * 16 + (lane & 7) + ((lane >> 4) & 1) * 8;
        xorB[np] = rowB[np] & 7;
    }
    const int cgB = (lane >> 3) & 1;

    float acc[2][4][4];
    #pragma unroll
    for (int mt = 0; mt < 2; mt++)
        #pragma unroll
        for (int nt = 0; nt < 4; nt++)
            #pragma unroll
            for (int e = 0; e < 4; e++) acc[mt][nt][e] = 0.f;

    load_chunk(0, 0); CP_COMMIT();
    for (int c = 0; c < 16; ++c) {
        const int buf = c & 1;
        if (c < 15) { load_chunk(c + 1, (c + 1) & 1); CP_COMMIT(); CP_WAIT(1); }
        else        { CP_WAIT(0); }
        __syncthreads();
        const uint32_t sb = sbase + buf * 49152;
        const uint32_t aHi = sb, aLo = sb + 16384, bHi = sb + 32768, bLo = sb + 40960;
        #pragma unroll
        for (int ks = 0; ks < 4; ks++) {
            uint32_t ah[2][4], al[2][4], bh2[2][4], bl2[2][4];
            #pragma unroll
            for (int mt = 0; mt < 2; mt++) {
                uint32_t off = (uint32_t)(rowA[mt] * 128) + (uint32_t)(((ks*2+cgA) ^ xorA[mt]) << 4);
                LDSM4(ah[mt][0], ah[mt][1], ah[mt][2], ah[mt][3], aHi + off);
                LDSM4(al[mt][0], al[mt][1], al[mt][2], al[mt][3], aLo + off);
            }
            #pragma unroll
            for (int np = 0; np < 2; np++) {
                uint32_t off = (uint32_t)(rowB[np] * 128) + (uint32_t)(((ks*2+cgB) ^ xorB[np]) << 4);
                LDSM4(bh2[np][0], bh2[np][1], bh2[np][2], bh2[np][3], bHi + off);
                LDSM4(bl2[np][0], bl2[np][1], bl2[np][2], bl2[np][3], bLo + off);
            }
            #pragma unroll
            for (int mt = 0; mt < 2; mt++)
                #pragma unroll
                for (int nt = 0; nt < 4; nt++) {
                    const int np = nt >> 1, h = (nt & 1) * 2;
                    MMA16816(acc[mt][nt], ah[mt][0],ah[mt][1],ah[mt][2],ah[mt][3], bh2[np][h], bh2[np][h+1]);
                    MMA16816(acc[mt][nt], ah[mt][0],ah[mt][1],ah[mt][2],ah[mt][3], bl2[np][h], bl2[np][h+1]);
                    MMA16816(acc[mt][nt], al[mt][0],al[mt][1],al[mt][2],al[mt][3], bh2[np][h], bh2[np][h+1]);
                }
        }
        __syncthreads();
    }

    #pragma unroll
    for (int mt = 0; mt < 2; mt++) {
        const int ma = m0 + wm + mt * 16 + (lane >> 2);
        const int mb2 = ma + 8;
        #pragma unroll
        for (int nt = 0; nt < 4; nt++) {
            const int n = n0 + wn + nt * 8 + 2 * (lane & 3);
            const float b0 = bo[n], b1 = bo[n + 1];
            *(float2*)(out + (size_t)ma * 1024 + n)  = make_float2(acc[mt][nt][0] + b0, acc[mt][nt][1] + b1);
            *(float2*)(out + (size_t)mb2 * 1024 + n) = make_float2(acc[mt][nt][2] + b0, acc[mt][nt][3] + b1);
        }
    }
}

// ---------------- kernel_launch ----------------
extern "C" void kernel_launch(void* const* d_in, const int* in_sizes, int n_in,
                              void* d_out, int out_size)
{
    (void)in_sizes; (void)n_in; (void)out_size;
    const float* q   = (const float*)d_in[0];
    const float* k   = (const float*)d_in[1];
    const float* v   = (const float*)d_in[2];
    const float* Wq  = (const float*)d_in[3];
    const float* bq  = (const float*)d_in[4];
    const float* Wk  = (const float*)d_in[5];
    const float* bk  = (const float*)d_in[6];
    const float* Wv  = (const float*)d_in[7];
    const float* bv  = (const float*)d_in[8];
    const float* Wo  = (const float*)d_in[9];
    const float* bo  = (const float*)d_in[10];
    const int*  mask = (const int*) d_in[11];
    float* out = (float*)d_out;

    __nv_bfloat16 *uwh, *uwl, *vwh, *vwl, *qh, *ql, *kh, *kl, *vh, *vl, *aoh, *aol, *woh, *wol;
    float* mw;
    uint32_t* mb;
    cudaGetSymbolAddress((void**)&uwh, g_uwh);   cudaGetSymbolAddress((void**)&uwl, g_uwl);
    cudaGetSymbolAddress((void**)&vwh, g_vwh);   cudaGetSymbolAddress((void**)&vwl, g_vwl);
    cudaGetSymbolAddress((void**)&mw, g_mw);
    cudaGetSymbolAddress((void**)&qh, g_qh);     cudaGetSymbolAddress((void**)&ql, g_ql);
    cudaGetSymbolAddress((void**)&kh, g_kh);     cudaGetSymbolAddress((void**)&kl, g_kl);
    cudaGetSymbolAddress((void**)&vh, g_vh);     cudaGetSymbolAddress((void**)&vl, g_vl);
    cudaGetSymbolAddress((void**)&aoh, g_aoh);   cudaGetSymbolAddress((void**)&aol, g_aol);
    cudaGetSymbolAddress((void**)&woh, g_woh);   cudaGetSymbolAddress((void**)&wol, g_wol);
    cudaGetSymbolAddress((void**)&mb, g_mb);

    cudaFuncSetAttribute(wino_gemm_kernel, cudaFuncAttributeMaxDynamicSharedMemorySize, GEMM_SMEM_BYTES);
    cudaFuncSetAttribute(flash_kernel,     cudaFuncAttributeMaxDynamicSharedMemorySize, FA_SMEM_BYTES);
    cudaFuncSetAttribute(proj_mma_kernel,  cudaFuncAttributeMaxDynamicSharedMemorySize, GEMM_SMEM_BYTES);

    prep_kernel<<<55296, 256>>>(q, k, v, Wq, Wk, Wv, Wo, mask,
                                vwh, vwl, uwh, uwl, woh, wol, mb);

    wino_gemm_kernel<<<dim3(8, 8, 108), 256, GEMM_SMEM_BYTES>>>(uwh, uwl, vwh, vwl, mw);
    wino_out_kernel<<<6144, 256>>>(mw, bq, bk, bv, qh, ql, kh, kl, vh, vl);

    flash_kernel<<<dim3(8, 128), 256, FA_SMEM_BYTES>>>(
        qh, ql, kh, kl, vh, vl, mb, aoh, aol);

    proj_mma_kernel<<<dim3(64, 16), 256, GEMM_SMEM_BYTES>>>(aoh, aol, woh, wol, bo, out);
}

// round 17
// speedup vs baseline: 1.0201x; 1.0012x over previous
#include <cuda_runtime.h>
#include <cuda_bf16.h>
#include <cstdint>
#include <math.h>

__device__ __forceinline__ uint32_t smem_to_u32(const void* p) {
    uint32_t a;
    asm("{ .reg .u64 t; cvta.to.shared.u64 t, %1; cvt.u32.u64 %0, t; }" : "=r"(a) : "l"(p));
    return a;
}
#define CP_ASYNC16(d, s) asm volatile("cp.async.cg.shared.global [%0], [%1], 16;" :: "r"(d), "l"(s))
#define CP_COMMIT() asm volatile("cp.async.commit_group;")
#define CP_WAIT(N)  asm volatile("cp.async.wait_group %0;" :: "n"(N))
#define LDSM4(R0,R1,R2,R3,A) \
    asm volatile("ldmatrix.sync.aligned.m8n8.x4.shared.b16 {%0,%1,%2,%3}, [%4];" \
        : "=r"(R0),"=r"(R1),"=r"(R2),"=r"(R3) : "r"(A))
#define LDSM4T(R0,R1,R2,R3,A) \
    asm volatile("ldmatrix.sync.aligned.m8n8.x4.trans.shared.b16 {%0,%1,%2,%3}, [%4];" \
        : "=r"(R0),"=r"(R1),"=r"(R2),"=r"(R3) : "r"(A))
#define MMA16816(D,A0,A1,A2,A3,B0,B1) \
    asm volatile("mma.sync.aligned.m16n8k16.row.col.f32.bf16.bf16.f32 " \
        "{%0,%1,%2,%3}, {%4,%5,%6,%7}, {%8,%9}, {%0,%1,%2,%3};" \
        : "+f"((D)[0]),"+f"((D)[1]),"+f"((D)[2]),"+f"((D)[3]) \
        : "r"(A0),"r"(A1),"r"(A2),"r"(A3),"r"(B0),"r"(B1))

__device__ __forceinline__ void pack_hilo(float v0, float v1, uint32_t& hi, uint32_t& lo) {
    uint32_t h;
    asm("cvt.rn.bf16x2.f32 %0, %1, %2;" : "=r"(h) : "f"(v1), "f"(v0));
    float l0 = v0 - __uint_as_float(h << 16);
    float l1 = v1 - __uint_as_float(h & 0xffff0000u);
    asm("cvt.rn.bf16x2.f32 %0, %1, %2;" : "=r"(lo) : "f"(l1), "f"(l0));
    hi = h;
}

// ---------------- scratch ----------------
#define QKV_ELEMS (8u * 1024u * 1024u)
#define UW_ELEMS  (108ull * 1024u * 1024u)
#define VW_ELEMS  (108ull * 512u * 1024u)
__device__ __align__(128) __nv_bfloat16 g_uwh[UW_ELEMS], g_uwl[UW_ELEMS];
__device__ __align__(128) __nv_bfloat16 g_vwh[VW_ELEMS], g_vwl[VW_ELEMS];
__device__ __align__(128) float g_mw[108ull * 1024u * 512u];
__device__ __align__(128) __nv_bfloat16 g_qh[QKV_ELEMS], g_ql[QKV_ELEMS];
__device__ __align__(128) __nv_bfloat16 g_kh[QKV_ELEMS], g_kl[QKV_ELEMS];
__device__ __align__(128) __nv_bfloat16 g_vh[QKV_ELEMS], g_vl[QKV_ELEMS];
__device__ __align__(128) __nv_bfloat16 g_aoh[QKV_ELEMS], g_aol[QKV_ELEMS];
__device__ __align__(128) __nv_bfloat16 g_woh[1024u*1024u], g_wol[1024u*1024u];
__device__ __align__(128) uint32_t g_mb[8u * 1024u * 32u];

// ---------------- Winograd transform helpers ----------------
__device__ __forceinline__ void gtrans(float a, float b, float d, float* y) {
    const float s6 = 1.f / 6.f, s12 = 1.f / 12.f, s24 = 1.f / 24.f;
    y[0] = 0.25f * a;
    y[1] = -(a + b + d) * s6;
    y[2] = (-a + b - d) * s6;
    y[3] = a * s24 + b * s12 + d * s6;
    y[4] = a * s24 - b * s12 + d * s6;
    y[5] = d;
}
__device__ __forceinline__ void btrans(const float* x, float* y) {
    y[0] = 4.f * x[0] - 5.f * x[2] + x[4];
    y[1] = -4.f * x[1] - 4.f * x[2] + x[3] + x[4];
    y[2] = 4.f * x[1] - 4.f * x[2] - x[3] + x[4];
    y[3] = -2.f * x[1] - x[2] + 2.f * x[3] + x[4];
    y[4] = 2.f * x[1] - x[2] - 2.f * x[3] + x[4];
    y[5] = 4.f * x[1] - 5.f * x[3] + x[5];
}
__device__ __forceinline__ void atrans(const float* x, float* y) {
    y[0] = x[0] + x[1] + x[2] + x[3] + x[4];
    y[1] = x[1] - x[2] + 2.f * x[3] - 2.f * x[4];
    y[2] = x[1] + x[2] + 4.f * x[3] + 4.f * x[4];
    y[3] = x[1] - x[2] + 8.f * x[3] - 8.f * x[4] + x[5];
}

// ====================================================================
// Merged prep kernel
// ====================================================================
__global__ __launch_bounds__(256)
void prep_kernel(const float* __restrict__ q, const float* __restrict__ k,
                 const float* __restrict__ v,
                 const float* __restrict__ Wq, const float* __restrict__ Wk,
                 const float* __restrict__ Wv, const float* __restrict__ Wo,
                 const int* __restrict__ mask,
                 __nv_bfloat16* __restrict__ vwh, __nv_bfloat16* __restrict__ vwl,
                 __nv_bfloat16* __restrict__ uh,  __nv_bfloat16* __restrict__ ul,
                 __nv_bfloat16* __restrict__ woh, __nv_bfloat16* __restrict__ wol,
                 uint32_t* __restrict__ mb) {
    __shared__ float xs[6][32][34];
    const int bx = blockIdx.x, tid = threadIdx.x;

    if (bx < 6144) {
        const int ty = bx & 7, ci0 = ((bx >> 3) & 31) * 32;
        const int zz = bx >> 8;
        const int conv = zz >> 3, b = zz & 7;
        const float* x = conv == 0 ? q : (conv == 1 ? k : v);
        for (int l = tid; l < 6 * 32 * 34; l += 256) {
            int u = l / 1088;
            int rem = l - u * 1088;
            int ci = rem / 34, cc = rem - ci * 34;
            int gr = 4 * ty - 1 + u, gc = cc - 1;
            float val = 0.f;
            if ((unsigned)gr < 32u && (unsigned)gc < 32u)
                val = x[((size_t)(b * 1024 + ci0 + ci)) * 1024 + gr * 32 + gc];
            xs[u][ci][cc] = val;
        }
        __syncthreads();
        const int tx = tid >> 5, ci = tid & 31;
        float d[6][6];
        #pragma unroll
        for (int u = 0; u < 6; u++)
            #pragma unroll
            for (int vv = 0; vv < 6; vv++) d[u][vv] = xs[u][ci][4 * tx + vv];
        float t1[6][6];
        #pragma unroll
        for (int vv = 0; vv < 6; vv++) {
            float col[6] = {d[0][vv], d[1][vv], d[2][vv], d[3][vv], d[4][vv], d[5][vv]};
            float y[6];
            btrans(col, y);
            #pragma unroll
            for (int u = 0; u < 6; u++) t1[u][vv] = y[u];
        }
        const size_t tile = (size_t)b * 64 + ty * 8 + tx;
        #pragma unroll
        for (int u = 0; u < 6; u++) {
            float y[6];
            btrans(t1[u], y);
            #pragma unroll
            for (int vv = 0; vv < 6; vv++) {
                int kk = u * 6 + vv;
                size_t o = ((size_t)(conv * 36 + kk) * 512 + tile) * 1024 + ci0 + ci;
                __nv_bfloat16 h = __float2bfloat16(y[vv]);
                vwh[o] = h;
                vwl[o] = __float2bfloat16(y[vv] - __bfloat162float(h));
            }
        }
    } else if (bx < 18432) {
        int i = (bx - 6144) * 256 + tid;
        int conv = i >> 20;
        int co = (i >> 10) & 1023, ci = i & 1023;
        const float* W = conv == 0 ? Wq : (conv == 1 ? Wk : Wv);
        const float* g = W + ((size_t)co * 1024 + ci) * 9;
        float t[6][3];
        #pragma unroll
        for (int c = 0; c < 3; c++) {
            float col[6];
            gtrans(g[c], g[3 + c], g[6 + c], col);
            #pragma unroll
            for (int u = 0; u < 6; u++) t[u][c] = col[u];
        }
        #pragma unroll
        for (int u = 0; u < 6; u++) {
            float U[6];
            gtrans(t[u][0], t[u][1], t[u][2], U);
            #pragma unroll
            for (int vv = 0; vv < 6; vv++) {
                int kk = u * 6 + vv;
                size_t o = (((size_t)(conv * 36 + kk)) << 20) + ((size_t)co << 10) + ci;
                __nv_bfloat16 h = __float2bfloat16(U[vv]);
                uh[o] = h;
                ul[o] = __float2bfloat16(U[vv] - __bfloat162float(h));
            }
        }
    } else if (bx < 22528) {
        int i = (bx - 18432) * 256 + tid;
        float w = Wo[i];
        __nv_bfloat16 h = __float2bfloat16(w);
        woh[i] = h;
        wol[i] = __float2bfloat16(w - __bfloat162float(h));
    } else {
        int idx = (bx - 22528) * 256 + tid;
        uint32_t word = __ballot_sync(0xffffffffu, mask[idx] != 0);
        if ((tid & 31) == 0) mb[idx >> 5] = word;
    }
}

// ====================================================================
// Winograd batched GEMM: M[g] = U[g] * V[g]^T.
// 128co x 64tile, 2-stage, 96KB smem -> 2 CTAs/SM, ONE barrier/iter.
// ====================================================================
#define GEMM_SMEM_BYTES (2 * 49152)

__global__ __launch_bounds__(256, 2)
void wino_gemm_kernel(const __nv_bfloat16* __restrict__ uh, const __nv_bfloat16* __restrict__ ul,
                      const __nv_bfloat16* __restrict__ vwh, const __nv_bfloat16* __restrict__ vwl,
                      float* __restrict__ mw) {
    extern __shared__ char dsm[];
    const int tid = threadIdx.x, wid = tid >> 5, lane = tid & 31;
    const int m0 = blockIdx.x * 128, n0 = blockIdx.y * 64, gidx = blockIdx.z;
    const __nv_bfloat16* ah_g = uh  + ((size_t)gidx << 20);
    const __nv_bfloat16* al_g = ul  + ((size_t)gidx << 20);
    const __nv_bfloat16* bh_g = vwh + ((size_t)gidx << 19);
    const __nv_bfloat16* bl_g = vwl + ((size_t)gidx << 19);
    const uint32_t sbase = smem_to_u32(dsm);
    const int rowb = tid >> 3, seg = tid & 7;

    auto load_chunk = [&](int c, int buf) {
        const int ci0 = c << 6;
        const uint32_t sb = sbase + buf * 49152;
        #pragma unroll
        for (int i = 0; i < 4; i++) {
            int row = rowb + 32 * i;
            uint32_t sw = (uint32_t)(row * 128) + (uint32_t)(((seg ^ (row & 7)) << 4));
            size_t ao = (size_t)(m0 + row) * 1024 + ci0 + seg * 8;
            CP_ASYNC16(sb + sw,         ah_g + ao);
            CP_ASYNC16(sb + 16384 + sw, al_g + ao);
            if (i < 2) {
                size_t bo = (size_t)(n0 + row) * 1024 + ci0 + seg * 8;
                CP_ASYNC16(sb + 32768 + sw, bh_g + bo);
                CP_ASYNC16(sb + 40960 + sw, bl_g + bo);
            }
        }
    };

    const int wm = (wid & 3) * 32, wn = (wid >> 2) * 32;
    int rowA[2], xorA[2];
    #pragma unroll
    for (int mt = 0; mt < 2; mt++) { rowA[mt] = wm + mt * 16 + (lane & 15); xorA[mt] = rowA[mt] & 7; }
    const int cgA = lane >> 4;
    int rowB[2], xorB[2];
    #pragma unroll
    for (int np = 0; np < 2; np++) {
        rowB[np] = wn + np * 16 + (lane & 7) + ((lane >> 4) & 1) * 8;
        xorB[np] = rowB[np] & 7;
    }
    const int cgB = (lane >> 3) & 1;

    float acc[2][4][4];
    #pragma unroll
    for (int mt = 0; mt < 2; mt++)
        #pragma unroll
        for (int nt = 0; nt < 4; nt++)
            #pragma unroll
            for (int e = 0; e < 4; e++) acc[mt][nt][e] = 0.f;

    load_chunk(0, 0); CP_COMMIT();
    for (int c = 0; c < 16; ++c) {
        CP_WAIT(0);
        __syncthreads();
        if (c < 15) { load_chunk(c + 1, (c + 1) & 1); CP_COMMIT(); }
        const uint32_t sb = sbase + (c & 1) * 49152;
        const uint32_t aHi = sb, aLo = sb + 16384, bHi = sb + 32768, bLo = sb + 40960;
        #pragma unroll
        for (int ks = 0; ks < 4; ks++) {
            uint32_t ah[2][4], al[2][4], bh2[2][4], bl2[2][4];
            #pragma unroll
            for (int mt = 0; mt < 2; mt++) {
                uint32_t off = (uint32_t)(rowA[mt] * 128) + (uint32_t)(((ks*2+cgA) ^ xorA[mt]) << 4);
                LDSM4(ah[mt][0], ah[mt][1], ah[mt][2], ah[mt][3], aHi + off);
                LDSM4(al[mt][0], al[mt][1], al[mt][2], al[mt][3], aLo + off);
            }
            #pragma unroll
            for (int np = 0; np < 2; np++) {
                uint32_t off = (uint32_t)(rowB[np] * 128) + (uint32_t)(((ks*2+cgB) ^ xorB[np]) << 4);
                LDSM4(bh2[np][0], bh2[np][1], bh2[np][2], bh2[np][3], bHi + off);
                LDSM4(bl2[np][0], bl2[np][1], bl2[np][2], bl2[np][3], bLo + off);
            }
            #pragma unroll
            for (int mt = 0; mt < 2; mt++)
                #pragma unroll
                for (int nt = 0; nt < 4; nt++) {
                    const int np = nt >> 1, h = (nt & 1) * 2;
                    MMA16816(acc[mt][nt], ah[mt][0],ah[mt][1],ah[mt][2],ah[mt][3], bh2[np][h], bh2[np][h+1]);
                    MMA16816(acc[mt][nt], ah[mt][0],ah[mt][1],ah[mt][2],ah[mt][3], bl2[np][h], bl2[np][h+1]);
                    MMA16816(acc[mt][nt], al[mt][0],al[mt][1],al[mt][2],al[mt][3], bh2[np][h], bh2[np][h+1]);
                }
        }
    }

    float* outp = mw + (size_t)gidx * 1024 * 512;
    #pragma unroll
    for (int mt = 0; mt < 2; mt++) {
        const int ma = m0 + wm + mt * 16 + (lane >> 2);
        const int mb2 = ma + 8;
        #pragma unroll
        for (int nt = 0; nt < 4; nt++) {
            const int n = n0 + wn + nt * 8 + 2 * (lane & 3);
            *(float2*)(outp + (size_t)ma  * 512 + n) = make_float2(acc[mt][nt][0], acc[mt][nt][1]);
            *(float2*)(outp + (size_t)mb2 * 512 + n) = make_float2(acc[mt][nt][2], acc[mt][nt][3]);
        }
    }
}

// ---------------- Winograd output transform: Y = A^T M A (2 tiles/thread) ----------------
__global__ __launch_bounds__(256)
void wino_out_kernel(const float* __restrict__ mw,
                     const float* __restrict__ bq, const float* __restrict__ bk,
                     const float* __restrict__ bv,
                     __nv_bfloat16* __restrict__ qh, __nv_bfloat16* __restrict__ ql,
                     __nv_bfloat16* __restrict__ kh, __nv_bfloat16* __restrict__ kl,
                     __nv_bfloat16* __restrict__ vh, __nv_bfloat16* __restrict__ vl) {
    const int idx = blockIdx.x * 256 + threadIdx.x;   // < 3 * 1024 * 256
    const int conv = idx >> 18;
    const int rem = idx & 0x3FFFF;
    const int co = rem >> 8;
    const int tp = rem & 255;           // tile pair: tiles 2tp, 2tp+1

    float Ma[36], Mb[36];
    #pragma unroll
    for (int kk = 0; kk < 36; kk++) {
        float2 m2 = *(const float2*)(mw + (size_t)(conv * 36 + kk) * 524288 +
                                     (size_t)co * 512 + 2 * tp);
        Ma[kk] = m2.x; Mb[kk] = m2.y;
    }

    float ta[4][6], tb[4][6];
    #pragma unroll
    for (int vv = 0; vv < 6; vv++) {
        float colA[6] = {Ma[vv], Ma[6+vv], Ma[12+vv], Ma[18+vv], Ma[24+vv], Ma[30+vv]};
        float colB[6] = {Mb[vv], Mb[6+vv], Mb[12+vv], Mb[18+vv], Mb[24+vv], Mb[30+vv]};
        float ya[4], yb[4];
        atrans(colA, ya);
        atrans(colB, yb);
        #pragma unroll
        for (int r = 0; r < 4; r++) { ta[r][vv] = ya[r]; tb[r][vv] = yb[r]; }
    }

    __nv_bfloat16 *oh, *ol;
    const float* bias;
    if (conv == 0)      { oh = qh; ol = ql; bias = bq; }
    else if (conv == 1) { oh = kh; ol = kl; bias = bk; }
    else                { oh = vh; ol = vl; bias = bv; }
    const float scale = (conv == 0) ? 0.125f : 1.0f;
    const float bi = bias[co];

    const int t0 = 2 * tp;
    const int b = t0 >> 6, tt = t0 & 63;
    const int tyy = tt >> 3, txx = tt & 7;           // txx even
    size_t base = ((size_t)(b * 1024 + co)) * 1024 + (4 * tyy) * 32 + 4 * txx;
    #pragma unroll
    for (int r = 0; r < 4; r++) {
        float ya[4], yb[4];
        atrans(ta[r], ya);
        atrans(tb[r], yb);
        uint32_t ha0, la0, ha1, la1, hb0, lb0, hb1, lb1;
        pack_hilo((ya[0] + bi) * scale, (ya[1] + bi) * scale, ha0, la0);
        pack_hilo((ya[2] + bi) * scale, (ya[3] + bi) * scale, ha1, la1);
        pack_hilo((yb[0] + bi) * scale, (yb[1] + bi) * scale, hb0, lb0);
        pack_hilo((yb[2] + bi) * scale, (yb[3] + bi) * scale, hb1, lb1);
        size_t o = base + (size_t)r * 32;
        uint4 hv = make_uint4(ha0, ha1, hb0, hb1);
        uint4 lv = make_uint4(la0, la1, lb0, lb1);
        *(uint4*)(oh + o) = hv;
        *(uint4*)(ol + o) = lv;
    }
}

// ====================================================================
// Fused flash attention. KV chunk = 64 rows, 16 chunks, 2 CTAs/SM,
// one barrier per chunk.
// ====================================================================
#define FA_KVBUF 32768
#define FA_QOFF  (2 * FA_KVBUF)
#define FA_MOFF  (FA_QOFF + 32768)
#define FA_SMEM_BYTES (FA_MOFF + 128 * 33 * 4)

__global__ __launch_bounds__(256, 2)
void flash_kernel(const __nv_bfloat16* __restrict__ qh_g, const __nv_bfloat16* __restrict__ ql_g,
                  const __nv_bfloat16* __restrict__ kh_g, const __nv_bfloat16* __restrict__ kl_g,
                  const __nv_bfloat16* __restrict__ vh_g, const __nv_bfloat16* __restrict__ vl_g,
                  const uint32_t* __restrict__ mbits,
                  __nv_bfloat16* __restrict__ aoh_g, __nv_bfloat16* __restrict__ aol_g) {
    extern __shared__ char dsm[];
    const int tid = threadIdx.x, wid = tid >> 5, lane = tid & 31;
    const int t0 = blockIdx.x * 128, bh = blockIdx.y, b = bh >> 4, h = bh & 15;
    const uint32_t sb = smem_to_u32(dsm);
    uint32_t* msk = (uint32_t*)(dsm + FA_MOFF);
    const int rowb = tid >> 3, seg = tid & 7;
    const size_t rbase = (size_t)b * 1024;
    const int fcol = h * 64, wt0 = wid * 16;

    auto load_kv = [&](int c, int buf) {
        const uint32_t p = sb + buf * FA_KVBUF;
        const int s0 = c * 64;
        #pragma unroll
        for (int i = 0; i < 2; i++) {
            int row = rowb + 32 * i;
            uint32_t sw = (uint32_t)(row * 128) + (uint32_t)(((seg ^ (row & 7)) << 4));
            size_t go = (rbase + s0 + row) * 1024 + fcol + seg * 8;
            CP_ASYNC16(p + sw,         kh_g + go);
            CP_ASYNC16(p + 8192 + sw,  kl_g + go);
            CP_ASYNC16(p + 16384 + sw, vh_g + go);
            CP_ASYNC16(p + 24576 + sw, vl_g + go);
        }
    };

    #pragma unroll
    for (int i = 0; i < 4; i++) {
        int row = rowb + 32 * i;
        uint32_t sw = (uint32_t)(row * 128) + (uint32_t)(((seg ^ (row & 7)) << 4));
        size_t go = (rbase + t0 + row) * 1024 + fcol + seg * 8;
        CP_ASYNC16(sb + FA_QOFF + sw,         qh_g + go);
        CP_ASYNC16(sb + FA_QOFF + 16384 + sw, ql_g + go);
    }
    #pragma unroll
    for (int j = 0; j < 16; j++) {
        int idx = tid + 256 * j;
        int r = idx >> 5, w = idx & 31;
        msk[r * 33 + w] = mbits[((size_t)b * 1024 + t0 + r) * 32 + w];
    }
    load_kv(0, 0); CP_COMMIT();

    float m0 = -INFINITY, m1 = -INFINITY, l0 = 0.f, l1 = 0.f;
    float o[8][4];
    #pragma unroll
    for (int j = 0; j < 8; j++)
        #pragma unroll
        for (int e = 0; e < 4; e++) o[j][e] = 0.f;
    const int lr0 = wt0 + (lane >> 2);

    #pragma unroll 1
    for (int c = 0; c < 16; c++) {
        CP_WAIT(0);
        __syncthreads();
        if (c < 15) { load_kv(c + 1, (c + 1) & 1); CP_COMMIT(); }
        const uint32_t kv = sb + (c & 1) * FA_KVBUF;

        uint32_t qfh[4][4], qfl[4][4];
        {
            const int rA = wt0 + (lane & 15), cg = lane >> 4;
            #pragma unroll
            for (int ks = 0; ks < 4; ks++) {
                uint32_t off = (uint32_t)(rA * 128) + (uint32_t)((((ks*2+cg)) ^ (rA & 7)) << 4);
                LDSM4(qfh[ks][0], qfh[ks][1], qfh[ks][2], qfh[ks][3], sb + FA_QOFF + off);
                LDSM4(qfl[ks][0], qfl[ks][1], qfl[ks][2], qfl[ks][3], sb + FA_QOFF + 16384 + off);
            }
        }

        float s[8][4];
        #pragma unroll
        for (int i = 0; i < 8; i++)
            #pragma unroll
            for (int e = 0; e < 4; e++) s[i][e] = 0.f;
        #pragma unroll
        for (int np = 0; np < 4; np++) {
            const int rB = np * 16 + (lane & 7) + ((lane >> 4) & 1) * 8;
            const int cg = (lane >> 3) & 1;
            #pragma unroll
            for (int ks = 0; ks < 4; ks++) {
                uint32_t off = (uint32_t)(rB * 128) + (uint32_t)((((ks*2+cg)) ^ (rB & 7)) << 4);
                uint32_t k4[4], kl4[4];
                LDSM4(k4[0], k4[1], k4[2], k4[3], kv + off);
                LDSM4(kl4[0], kl4[1], kl4[2], kl4[3], kv + 8192 + off);
                MMA16816(s[2*np],   qfh[ks][0],qfh[ks][1],qfh[ks][2],qfh[ks][3], k4[0], k4[1]);
                MMA16816(s[2*np],   qfh[ks][0],qfh[ks][1],qfh[ks][2],qfh[ks][3], kl4[0], kl4[1]);
                MMA16816(s[2*np],   qfl[ks][0],qfl[ks][1],qfl[ks][2],qfl[ks][3], k4[0], k4[1]);
                MMA16816(s[2*np+1], qfh[ks][0],qfh[ks][1],qfh[ks][2],qfh[ks][3], k4[2], k4[3]);
                MMA16816(s[2*np+1], qfh[ks][0],qfh[ks][1],qfh[ks][2],qfh[ks][3], kl4[2], kl4[3]);
                MMA16816(s[2*np+1], qfl[ks][0],qfl[ks][1],qfl[ks][2],qfl[ks][3], k4[2], k4[3]);
            }
        }

        float cm0 = -3.4e38f, cm1 = -3.4e38f;
        #pragma unroll
        for (int nt = 0; nt < 8; nt++) {
            const int bp = (8 * nt + 2 * (lane & 3)) & 31;
            const uint32_t wa = msk[lr0 * 33 + c * 2 + (nt >> 2)];
            const uint32_t wb = msk[(lr0 + 8) * 33 + c * 2 + (nt >> 2)];
            if (!((wa >> bp) & 1))       s[nt][0] = -1e9f;
            if (!((wa >> (bp + 1)) & 1)) s[nt][1] = -1e9f;
            if (!((wb >> bp) & 1))       s[nt][2] = -1e9f;
            if (!((wb >> (bp + 1)) & 1)) s[nt][3] = -1e9f;
            cm0 = fmaxf(cm0, fmaxf(s[nt][0], s[nt][1]));
            cm1 = fmaxf(cm1, fmaxf(s[nt][2], s[nt][3]));
        }
        cm0 = fmaxf(cm0, __shfl_xor_sync(0xffffffffu, cm0, 1));
        cm0 = fmaxf(cm0, __shfl_xor_sync(0xffffffffu, cm0, 2));
        cm1 = fmaxf(cm1, __shfl_xor_sync(0xffffffffu, cm1, 1));
        cm1 = fmaxf(cm1, __shfl_xor_sync(0xffffffffu, cm1, 2));
        float mn0 = fmaxf(m0, cm0), mn1 = fmaxf(m1, cm1);
        float sc0 = __expf(m0 - mn0), sc1 = __expf(m1 - mn1);
        m0 = mn0; m1 = mn1;
        float rs0 = 0.f, rs1 = 0.f;
        #pragma unroll
        for (int nt = 0; nt < 8; nt++) {
            s[nt][0] = __expf(s[nt][0] - mn0); s[nt][1] = __expf(s[nt][1] - mn0);
            s[nt][2] = __expf(s[nt][2] - mn1); s[nt][3] = __expf(s[nt][3] - mn1);
            rs0 += s[nt][0] + s[nt][1];
            rs1 += s[nt][2] + s[nt][3];
        }
        l0 = l0 * sc0 + rs0; l1 = l1 * sc1 + rs1;
        #pragma unroll
        for (int j = 0; j < 8; j++) {
            o[j][0] *= sc0; o[j][1] *= sc0; o[j][2] *= sc1; o[j][3] *= sc1;
        }

        #pragma unroll
        for (int ks = 0; ks < 4; ks++) {
            uint32_t ph[4], pl[4];
            pack_hilo(s[2*ks][0],   s[2*ks][1],   ph[0], pl[0]);
            pack_hilo(s[2*ks][2],   s[2*ks][3],   ph[1], pl[1]);
            pack_hilo(s[2*ks+1][0], s[2*ks+1][1], ph[2], pl[2]);
            pack_hilo(s[2*ks+1][2], s[2*ks+1][3], ph[3], pl[3]);
            const int vrow = ks * 16 + (lane & 7) + 8 * ((lane >> 3) & 1);
            #pragma unroll
            for (int ds = 0; ds < 4; ds++) {
                uint32_t off = (uint32_t)(vrow * 128) +
                               (uint32_t)((((ds*2 + (lane >> 4))) ^ (vrow & 7)) << 4);
                uint32_t v4[4], vl4[4];
                LDSM4T(v4[0], v4[1], v4[2], v4[3], kv + 16384 + off);
                LDSM4T(vl4[0], vl4[1], vl4[2], vl4[3], kv + 24576 + off);
                MMA16816(o[2*ds],   ph[0],ph[1],ph[2],ph[3], v4[0], v4[1]);
                MMA16816(o[2*ds],   ph[0],ph[1],ph[2],ph[3], vl4[0], vl4[1]);
                MMA16816(o[2*ds],   pl[0],pl[1],pl[2],pl[3], v4[0], v4[1]);
                MMA16816(o[2*ds+1], ph[0],ph[1],ph[2],ph[3], v4[2], v4[3]);
                MMA16816(o[2*ds+1], ph[0],ph[1],ph[2],ph[3], vl4[2], vl4[3]);
                MMA16816(o[2*ds+1], pl[0],pl[1],pl[2],pl[3], v4[2], v4[3]);
            }
        }
    }

    l0 += __shfl_xor_sync(0xffffffffu, l0, 1);
    l0 += __shfl_xor_sync(0xffffffffu, l0, 2);
    l1 += __shfl_xor_sync(0xffffffffu, l1, 1);
    l1 += __shfl_xor_sync(0xffffffffu, l1, 2);
    const float i0 = 1.f / l0, i1 = 1.f / l1;
    size_t ra = (rbase + t0 + lr0) * 1024 + fcol + 2 * (lane & 3);
    size_t rb2 = ra + 8 * 1024;
    #pragma unroll
    for (int j = 0; j < 8; j++) {
        uint32_t h0, lo0, h1, lo1;
        pack_hilo(o[j][0] * i0, o[j][1] * i0, h0, lo0);
        pack_hilo(o[j][2] * i1, o[j][3] * i1, h1, lo1);
        *(uint32_t*)(aoh_g + ra + 8*j)  = h0;
        *(uint32_t*)(aol_g + ra + 8*j)  = lo0;
        *(uint32_t*)(aoh_g + rb2 + 8*j) = h1;
        *(uint32_t*)(aol_g + rb2 + 8*j) = lo1;
    }
}

// ====================================================================
// Projection GEMM: 128 x 64 tile, 2-stage, 96KB, 2 CTAs/SM, 1 barrier/iter.
// ====================================================================
__global__ __launch_bounds__(256, 2)
void proj_mma_kernel(const __nv_bfloat16* __restrict__ ah_g, const __nv_bfloat16* __restrict__ al_g,
                     const __nv_bfloat16* __restrict__ wh_g, const __nv_bfloat16* __restrict__ wl_g,
                     const float* __restrict__ bo, float* __restrict__ out) {
    extern __shared__ char dsm[];
    const int tid = threadIdx.x, wid = tid >> 5, lane = tid & 31;
    const int m0 = blockIdx.x * 128, n0 = blockIdx.y * 64;
    const uint32_t sbase = smem_to_u32(dsm);
    const int rowb = tid >> 3, seg = tid & 7;

    auto load_chunk = [&](int c, int buf) {
        const int ci0 = c << 6;
        const uint32_t sb = sbase + buf * 49152;
        #pragma unroll
        for (int i = 0; i < 4; i++) {
            int row = rowb + 32 * i;
            uint32_t sw = (uint32_t)(row * 128) + (uint32_t)(((seg ^ (row & 7)) << 4));
            size_t ao = (size_t)(m0 + row) * 1024 + ci0 + seg * 8;
            CP_ASYNC16(sb + sw,         ah_g + ao);
            CP_ASYNC16(sb + 16384 + sw, al_g + ao);
            if (i < 2) {
                size_t wo = (size_t)(n0 + row) * 1024 + ci0 + seg * 8;
                CP_ASYNC16(sb + 32768 + sw, wh_g + wo);
                CP_ASYNC16(sb + 40960 + sw, wl_g + wo);
            }
        }
    };

    const int wm = (wid & 3) * 32, wn = (wid >> 2) * 32;
    int rowA[2], xorA[2];
    #pragma unroll
    for (int mt = 0; mt < 2; mt++) { rowA[mt] = wm + mt * 16 + (lane & 15); xorA[mt] = rowA[mt] & 7; }
    const int cgA = lane >> 4;
    int rowB[2], xorB[2];
    #pragma unroll
    for (int np = 0; np < 2; np++) {
        rowB[np] = wn + np * 16 + (lane & 7) + ((lane >> 4) & 1) * 8;
        xorB[np] = rowB[np] & 7;
    }
    const int cgB = (lane >> 3) & 1;

    float acc[2][4][4];
    #pragma unroll
    for (int mt = 0; mt < 2; mt++)
        #pragma unroll
        for (int nt = 0; nt < 4; nt++)
            #pragma unroll
            for (int e = 0; e < 4; e++) acc[mt][nt][e] = 0.f;

    load_chunk(0, 0); CP_COMMIT();
    for (int c = 0; c < 16; ++c) {
        CP_WAIT(0);
        __syncthreads();
        if (c < 15) { load_chunk(c + 1, (c + 1) & 1); CP_COMMIT(); }
        const uint32_t sb = sbase + (c & 1) * 49152;
        const uint32_t aHi = sb, aLo = sb + 16384, bHi = sb + 32768, bLo = sb + 40960;
        #pragma unroll
        for (int ks = 0; ks < 4; ks++) {
            uint32_t ah[2][4], al[2][4], bh2[2][4], bl2[2][4];
            #pragma unroll
            for (int mt = 0; mt < 2; mt++) {
                uint32_t off = (uint32_t)(rowA[mt] * 128) + (uint32_t)(((ks*2+cgA) ^ xorA[mt]) << 4);
                LDSM4(ah[mt][0], ah[mt][1], ah[mt][2], ah[mt][3], aHi + off);
                LDSM4(al[mt][0], al[mt][1], al[mt][2], al[mt][3], aLo + off);
            }
            #pragma unroll
            for (int np = 0; np < 2; np++) {
                uint32_t off = (uint32_t)(rowB[np] * 128) + (uint32_t)(((ks*2+cgB) ^ xorB[np]) << 4);
                LDSM4(bh2[np][0], bh2[np][1], bh2[np][2], bh2[np][3], bHi + off);
                LDSM4(bl2[np][0], bl2[np][1], bl2[np][2], bl2[np][3], bLo + off);
            }
            #pragma unroll
            for (int mt = 0; mt < 2; mt++)
                #pragma unroll
                for (int nt = 0; nt < 4; nt++) {
                    const int np = nt >> 1, h = (nt & 1) * 2;
                    MMA16816(acc[mt][nt], ah[mt][0],ah[mt][1],ah[mt][2],ah[mt][3], bh2[np][h], bh2[np][h+1]);
                    MMA16816(acc[mt][nt], ah[mt][0],ah[mt][1],ah[mt][2],ah[mt][3], bl2[np][h], bl2[np][h+1]);
                    MMA16816(acc[mt][nt], al[mt][0],al[mt][1],al[mt][2],al[mt][3], bh2[np][h], bh2[np][h+1]);
                }
        }
    }

    #pragma unroll
    for (int mt = 0; mt < 2; mt++) {
        const int ma = m0 + wm + mt * 16 + (lane >> 2);
        const int mb2 = ma + 8;
        #pragma unroll
        for (int nt = 0; nt < 4; nt++) {
            const int n = n0 + wn + nt * 8 + 2 * (lane & 3);
            const float b0 = bo[n], b1 = bo[n + 1];
            *(float2*)(out + (size_t)ma * 1024 + n)  = make_float2(acc[mt][nt][0] + b0, acc[mt][nt][1] + b1);
            *(float2*)(out + (size_t)mb2 * 1024 + n) = make_float2(acc[mt][nt][2] + b0, acc[mt][nt][3] + b1);
        }
    }
}

// ---------------- kernel_launch ----------------
extern "C" void kernel_launch(void* const* d_in, const int* in_sizes, int n_in,
                              void* d_out, int out_size)
{
    (void)in_sizes; (void)n_in; (void)out_size;
    const float* q   = (const float*)d_in[0];
    const float* k   = (const float*)d_in[1];
    const float* v   = (const float*)d_in[2];
    const float* Wq  = (const float*)d_in[3];
    const float* bq  = (const float*)d_in[4];
    const float* Wk  = (const float*)d_in[5];
    const float* bk  = (const float*)d_in[6];
    const float* Wv  = (const float*)d_in[7];
    const float* bv  = (const float*)d_in[8];
    const float* Wo  = (const float*)d_in[9];
    const float* bo  = (const float*)d_in[10];
    const int*  mask = (const int*) d_in[11];
    float* out = (float*)d_out;

    __nv_bfloat16 *uwh, *uwl, *vwh, *vwl, *qh, *ql, *kh, *kl, *vh, *vl, *aoh, *aol, *woh, *wol;
    float* mw;
    uint32_t* mb;
    cudaGetSymbolAddress((void**)&uwh, g_uwh);   cudaGetSymbolAddress((void**)&uwl, g_uwl);
    cudaGetSymbolAddress((void**)&vwh, g_vwh);   cudaGetSymbolAddress((void**)&vwl, g_vwl);
    cudaGetSymbolAddress((void**)&mw, g_mw);
    cudaGetSymbolAddress((void**)&qh, g_qh);     cudaGetSymbolAddress((void**)&ql, g_ql);
    cudaGetSymbolAddress((void**)&kh, g_kh);     cudaGetSymbolAddress((void**)&kl, g_kl);
    cudaGetSymbolAddress((void**)&vh, g_vh);     cudaGetSymbolAddress((void**)&vl, g_vl);
    cudaGetSymbolAddress((void**)&aoh, g_aoh);   cudaGetSymbolAddress((void**)&aol, g_aol);
    cudaGetSymbolAddress((void**)&woh, g_woh);   cudaGetSymbolAddress((void**)&wol, g_wol);
    cudaGetSymbolAddress((void**)&mb, g_mb);

    cudaFuncSetAttribute(wino_gemm_kernel, cudaFuncAttributeMaxDynamicSharedMemorySize, GEMM_SMEM_BYTES);
    cudaFuncSetAttribute(flash_kernel,     cudaFuncAttributeMaxDynamicSharedMemorySize, FA_SMEM_BYTES);
    cudaFuncSetAttribute(proj_mma_kernel,  cudaFuncAttributeMaxDynamicSharedMemorySize, GEMM_SMEM_BYTES);

    prep_kernel<<<55296, 256>>>(q, k, v, Wq, Wk, Wv, Wo, mask,
                                vwh, vwl, uwh, uwl, woh, wol, mb);

    wino_gemm_kernel<<<dim3(8, 8, 108), 256, GEMM_SMEM_BYTES>>>(uwh, uwl, vwh, vwl, mw);
    wino_out_kernel<<<3072, 256>>>(mw, bq, bk, bv, qh, ql, kh, kl, vh, vl);

    flash_kernel<<<dim3(8, 128), 256, FA_SMEM_BYTES>>>(
        qh, ql, kh, kl, vh, vl, mb, aoh, aol);

    proj_mma_kernel<<<dim3(64, 16), 256, GEMM_SMEM_BYTES>>>(aoh, aol, woh, wol, bo, out);
}